// round 10
// baseline (speedup 1.0000x reference)
#include <cuda_runtime.h>
#include <cuda_bf16.h>
#include <cstdint>
#include <math.h>

#define B_   512
#define L_   20
#define NS_  16
#define EPS_ 32
#define H_   128
#define V_   100000
#define NN_  (B_*NS_)   // 8192 nodes

#define SSTRIDE 130
#define SMEM_BYTES (2 * 128 * SSTRIDE * 4)

// ---------------- device scratch (no runtime allocation allowed) ----------------
__device__ float g_x[NN_*H_];
__device__ float g_m[NN_*H_];
__device__ float g_agg[NN_*H_];
__device__ float g_gt[H_*H_];
__device__ float g_gi[NN_*3*H_];
__device__ float g_gh[NN_*3*H_];
__device__ float g_hidden[B_*L_*H_];
__device__ float g_av[B_*H_];
// K=384 three-segment bf16 splits: A3=[hi|lo|hi], B3=[hi|hi|lo]
// => dot = hi*hi + lo*hi + hi*lo  (missing only lo*lo ~ 2^-18)
__device__ __nv_bfloat16 g_e3[(V_-1)*384];
__device__ __nv_bfloat16 g_a3[B_*384];

// packed fp32x2 FMA
#define FMA2(acc, a, b) asm("fma.rn.f32x2 %0, %1, %2, %0;" : "+l"(acc) : "l"(a), "l"(b))

// =================================================================================
// SIMT fp32 GEMM (middle ops): C[M,N] = A[M,128]*B[N,128]^T (+bias)
// =================================================================================
__global__ void __launch_bounds__(256, 1) gemm_tn128(
    const float* __restrict__ A, const float* __restrict__ B,
    const float* __restrict__ bias, float* __restrict__ C, int M, int N)
{
    extern __shared__ __align__(16) float smem[];
    float* As = smem;
    float* Bs = smem + 128*SSTRIDE;

    const int tid = threadIdx.x;
    const int m0 = blockIdx.y << 7;
    const int n0 = blockIdx.x << 7;

    {
        const float4* A4 = reinterpret_cast<const float4*>(A);
        const float4* B4 = reinterpret_cast<const float4*>(B);
#pragma unroll
        for (int i = tid; i < 128*32; i += 256) {
            int r = i >> 5, c = i & 31;
            float4 va = A4[(m0 + r)*32 + c];
            float2* pa = reinterpret_cast<float2*>(&As[r*SSTRIDE + 4*c]);
            pa[0] = make_float2(va.x, va.y);
            pa[1] = make_float2(va.z, va.w);
            int gr = n0 + r; gr = (gr < N) ? gr : (N - 1);
            float4 vb = B4[gr*32 + c];
            float2* pb = reinterpret_cast<float2*>(&Bs[r*SSTRIDE + 4*c]);
            pb[0] = make_float2(vb.x, vb.y);
            pb[1] = make_float2(vb.z, vb.w);
        }
    }
    __syncthreads();

    const int tx = tid & 15, ty = tid >> 4;
    unsigned long long acc[8][8];
#pragma unroll
    for (int i = 0; i < 8; i++)
#pragma unroll
        for (int j = 0; j < 8; j++) acc[i][j] = 0ull;

#pragma unroll 8
    for (int t = 0; t < 64; ++t) {
        unsigned long long a2[8], b2[8];
#pragma unroll
        for (int i = 0; i < 8; i++) {
            a2[i] = *reinterpret_cast<const unsigned long long*>(&As[(16*i + ty)*SSTRIDE + 2*t]);
            b2[i] = *reinterpret_cast<const unsigned long long*>(&Bs[(16*i + tx)*SSTRIDE + 2*t]);
        }
#pragma unroll
        for (int i = 0; i < 8; i++)
#pragma unroll
            for (int j = 0; j < 8; j++)
                FMA2(acc[i][j], a2[i], b2[j]);
    }

#pragma unroll
    for (int i = 0; i < 8; i++) {
        int row = m0 + ty + 16*i;
#pragma unroll
        for (int j = 0; j < 8; j++) {
            int col = n0 + tx + 16*j;
            if (col < N) {
                float2 p = *reinterpret_cast<float2*>(&acc[i][j]);
                float v = p.x + p.y;
                if (bias) v += bias[col];
                C[row * N + col] = v;
            }
        }
    }
}

// =================================================================================
// mma.sync bf16 scores GEMM: C[M,N] = A3[M,384] * B3[N,384]^T  (fp32 accum)
// 128x128 tile/CTA, 256 thr, 8 warps (2m x 4n), warp tile 64x32, m16n8k16.
// Smem rows padded to 392 bf16 (784B = 49 x 16B, odd) -> ldmatrix conflict-free.
// NOTE: N is odd (99999) -> epilogue must use scalar 32-bit stores only.
// =================================================================================
#define KK   384
#define ASTR 392
#define TCS_SMEM (2 * 128 * ASTR * 2)     // 200704 B

__device__ __forceinline__ uint32_t smem_u32(const void* p) {
    uint32_t a;
    asm("{ .reg .u64 t; cvta.to.shared.u64 t, %1; cvt.u32.u64 %0, t; }" : "=r"(a) : "l"(p));
    return a;
}
#define LDSM4(r0,r1,r2,r3,addr) \
    asm volatile("ldmatrix.sync.aligned.m8n8.x4.shared.b16 {%0,%1,%2,%3}, [%4];" \
        : "=r"(r0), "=r"(r1), "=r"(r2), "=r"(r3) : "r"(addr))
#define MMA16816(c, a, b0, b1) \
    asm volatile("mma.sync.aligned.m16n8k16.row.col.f32.bf16.bf16.f32 " \
        "{%0,%1,%2,%3}, {%4,%5,%6,%7}, {%8,%9}, {%0,%1,%2,%3};" \
        : "+f"((c)[0]), "+f"((c)[1]), "+f"((c)[2]), "+f"((c)[3]) \
        : "r"((a)[0]), "r"((a)[1]), "r"((a)[2]), "r"((a)[3]), "r"(b0), "r"(b1))

__global__ void __launch_bounds__(256, 1) scores_mma_k(
    const __nv_bfloat16* __restrict__ A3, const __nv_bfloat16* __restrict__ B3,
    float* __restrict__ C, int N)
{
    extern __shared__ __align__(16) __nv_bfloat16 smemb[];
    __nv_bfloat16* As = smemb;                 // [128][ASTR]
    __nv_bfloat16* Bs = smemb + 128*ASTR;      // [128][ASTR]

    const int tid = threadIdx.x;
    const int m0 = blockIdx.y << 7;
    const int n0 = blockIdx.x << 7;

    // Load tiles: 128 rows x 48 uint4 chunks each
    {
        const uint4* A4 = reinterpret_cast<const uint4*>(A3);
        const uint4* B4 = reinterpret_cast<const uint4*>(B3);
#pragma unroll
        for (int i = tid; i < 128*48; i += 256) {
            int r = i / 48, c = i % 48;
            *reinterpret_cast<uint4*>(&As[r*ASTR + c*8]) = A4[(m0 + r)*48 + c];
            int gr = n0 + r; gr = (gr < N) ? gr : (N - 1);
            *reinterpret_cast<uint4*>(&Bs[r*ASTR + c*8]) = B4[gr*48 + c];
        }
    }
    __syncthreads();

    const int lane = tid & 31, wid = tid >> 5;
    const int wm = wid >> 2, wn = wid & 3;     // warp tile: rows wm*64, cols wn*32

    // ldmatrix lane addressing
    uint32_t a_addr[4], b_addr[2];
#pragma unroll
    for (int mi = 0; mi < 4; mi++) {
        int arow = wm*64 + mi*16 + (lane & 15);
        int acol = (lane >> 4) * 8;
        a_addr[mi] = smem_u32(&As[arow*ASTR + acol]);
    }
#pragma unroll
    for (int njp = 0; njp < 2; njp++) {
        int brow = wn*32 + njp*16 + ((lane >> 4) & 1)*8 + (lane & 7);
        int bcol = ((lane >> 3) & 1) * 8;
        b_addr[njp] = smem_u32(&Bs[brow*ASTR + bcol]);
    }

    float acc[4][4][4];
#pragma unroll
    for (int i = 0; i < 4; i++)
#pragma unroll
        for (int j = 0; j < 4; j++)
#pragma unroll
            for (int q = 0; q < 4; q++) acc[i][j][q] = 0.f;

#pragma unroll 4
    for (int k = 0; k < KK/16; k++) {
        uint32_t a[4][4], b[2][4];
#pragma unroll
        for (int mi = 0; mi < 4; mi++)
            LDSM4(a[mi][0], a[mi][1], a[mi][2], a[mi][3], a_addr[mi] + k*32);
#pragma unroll
        for (int njp = 0; njp < 2; njp++)
            LDSM4(b[njp][0], b[njp][1], b[njp][2], b[njp][3], b_addr[njp] + k*32);
#pragma unroll
        for (int mi = 0; mi < 4; mi++)
#pragma unroll
            for (int nj = 0; nj < 4; nj++)
                MMA16816(acc[mi][nj], a[mi], b[nj >> 1][(nj & 1)*2], b[nj >> 1][(nj & 1)*2 + 1]);
    }

    // Epilogue: scalar fp32 stores only (N odd -> no 8B alignment guarantee).
#pragma unroll
    for (int mi = 0; mi < 4; mi++) {
        int r0 = m0 + wm*64 + mi*16 + (lane >> 2);
        long base0 = (long)r0 * N;
        long base1 = (long)(r0 + 8) * N;
#pragma unroll
        for (int nj = 0; nj < 4; nj++) {
            int c0 = n0 + wn*32 + nj*8 + (lane & 3)*2;
            if (c0 < N) {
                C[base0 + c0] = acc[mi][nj][0];
                C[base1 + c0] = acc[mi][nj][2];
                if (c0 + 1 < N) {
                    C[base0 + c0 + 1] = acc[mi][nj][1];
                    C[base1 + c0 + 1] = acc[mi][nj][3];
                }
            }
        }
    }
}

// ---------------- small kernels ----------------

// fp32 [n x 128] -> bf16 [n x 384]; mode 0 (B/emb): [hi|hi|lo], mode 1 (A): [hi|lo|hi]
__global__ void split3_bf16_k(const float* __restrict__ src, __nv_bfloat16* __restrict__ dst,
                              int n, int mode) {
    int i = blockIdx.x * 256 + threadIdx.x;
    if (i < n) {
        int row = i >> 7, col = i & 127;
        float v = src[i];
        __nv_bfloat16 h = __float2bfloat16(v);
        __nv_bfloat16 l = __float2bfloat16(v - __bfloat162float(h));
        __nv_bfloat16* d = dst + row*384 + col;
        if (mode == 0) { d[0] = h; d[128] = h; d[256] = l; }
        else           { d[0] = h; d[128] = l; d[256] = h; }
    }
}

__global__ void transpose128_k(const float* __restrict__ G, float* __restrict__ GT) {
    int i = blockIdx.x * 256 + threadIdx.x;
    int k = i >> 7, j = i & 127;
    GT[j*128 + k] = G[i];
}

__global__ void gather_x_k(const int* __restrict__ items, const float* __restrict__ emb,
                           float* __restrict__ x) {
    int n = blockIdx.x, t = threadIdx.x;
    x[n*H_ + t] = emb[items[n]*H_ + t];
}

__global__ void segsum_k(const float* __restrict__ m, const int* __restrict__ ei,
                         float* __restrict__ agg) {
    __shared__ float ms[NS_][H_];
    __shared__ float as[NS_][H_];
    int b = blockIdx.x, t = threadIdx.x;
#pragma unroll
    for (int j = 0; j < NS_; j++) { ms[j][t] = m[(b*NS_ + j)*H_ + t]; as[j][t] = 0.f; }
    __syncthreads();
    const int* src = ei + b*EPS_;
    const int* dst = ei + B_*EPS_ + b*EPS_;
#pragma unroll
    for (int e = 0; e < EPS_; e++) {
        int s = src[e] - b*NS_;
        int d = dst[e] - b*NS_;
        as[d][t] += ms[s][t];
    }
#pragma unroll
    for (int j = 0; j < NS_; j++) agg[(b*NS_ + j)*H_ + t] = as[j][t];
}

__global__ void gru_update_k(const float* __restrict__ gi, const float* __restrict__ gh,
                             float* __restrict__ x) {
    int i = blockIdx.x * 256 + threadIdx.x;
    int n = i >> 7, h = i & 127;
    const float* gin = gi + n*3*H_;
    const float* ghn = gh + n*3*H_;
    float ir = gin[h], iz = gin[H_ + h], in_ = gin[2*H_ + h];
    float hr = ghn[h], hz = ghn[H_ + h], hn  = ghn[2*H_ + h];
    float r = 1.f / (1.f + expf(-(ir + hr)));
    float z = 1.f / (1.f + expf(-(iz + hz)));
    float nn = tanhf(in_ + r*hn);
    x[i] = (1.f - z)*nn + z*x[i];
}

__global__ void build_hidden_k(const int* __restrict__ seq, const int* __restrict__ items,
                               const float* __restrict__ x, const float* __restrict__ emb,
                               float* __restrict__ hid) {
    int bl = blockIdx.x;
    int b = bl / L_, t = threadIdx.x;
    int s = seq[bl];
    float v = 0.f;
    if (s != 0) {
        int j = -1;
#pragma unroll
        for (int q = 0; q < NS_; q++) if (j < 0 && items[b*NS_ + q] == s) j = q;
        v = (j >= 0) ? x[(b*NS_ + j)*H_ + t] : emb[s*H_ + t];
    }
    hid[bl*H_ + t] = v;
}

__device__ __forceinline__ float bsum128(float v, float* s4) {
#pragma unroll
    for (int o = 16; o > 0; o >>= 1) v += __shfl_xor_sync(0xffffffffu, v, o);
    int w = threadIdx.x >> 5;
    if ((threadIdx.x & 31) == 0) s4[w] = v;
    __syncthreads();
    v = s4[0] + s4[1] + s4[2] + s4[3];
    __syncthreads();
    return v;
}

__global__ void attention_k(const float* __restrict__ hid_g, const int* __restrict__ mask,
                            const float* __restrict__ W1, const float* __restrict__ b1,
                            const float* __restrict__ W2, const float* __restrict__ b2,
                            const float* __restrict__ w3, const float* __restrict__ Wt,
                            const float* __restrict__ bt, const float* __restrict__ gamma,
                            const float* __restrict__ beta, float* __restrict__ outA)
{
    __shared__ float hid[L_][H_];
    __shared__ float a_sh[H_];
    __shared__ float red[4];
    int b = blockIdx.x, t = threadIdx.x;
#pragma unroll
    for (int l = 0; l < L_; l++) hid[l][t] = hid_g[(b*L_ + l)*H_ + t];
    int len = 0;
#pragma unroll
    for (int l = 0; l < L_; l++) len += mask[b*L_ + l];
    __syncthreads();

    const float* ht = hid[len - 1];
    float q1 = b1[t];
#pragma unroll 8
    for (int k = 0; k < H_; k++) q1 += W1[t*H_ + k] * ht[k];
    float w3t = w3[t];

    float acc = 0.f;
    for (int l = 0; l < L_; l++) {
        float q2 = b2[t];
#pragma unroll 8
        for (int k = 0; k < H_; k++) q2 += W2[t*H_ + k] * hid[l][k];
        float v = (1.f / (1.f + expf(-(q1 + q2)))) * w3t;
        float alpha = bsum128(v, red);
        acc += alpha * hid[l][t] * (float)mask[b*L_ + l];
    }
    a_sh[t] = acc;
    __syncthreads();

    float o = bt[t];
#pragma unroll 8
    for (int k = 0; k < H_; k++) o += Wt[t*2*H_ + k] * a_sh[k];
#pragma unroll 8
    for (int k = 0; k < H_; k++) o += Wt[t*2*H_ + H_ + k] * ht[k];

    float mu = bsum128(o, red) * (1.f / H_);
    float d = o - mu;
    float var = bsum128(d*d, red) * (1.f / H_);
    outA[b*H_ + t] = d * rsqrtf(var + 1e-5f) * gamma[t] + beta[t];
}

// =================================================================================
extern "C" void kernel_launch(void* const* d_in, const int* in_sizes, int n_in,
                              void* d_out, int out_size)
{
    const int*   items    = (const int*)d_in[0];
    const int*   edge     = (const int*)d_in[1];
    const int*   sequence = (const int*)d_in[2];
    const int*   mask     = (const int*)d_in[3];
    const float* emb      = (const float*)d_in[4];
    const float* ggnn_w   = (const float*)d_in[5];
    const float* W_ih     = (const float*)d_in[6];
    const float* W_hh     = (const float*)d_in[7];
    const float* b_ih     = (const float*)d_in[8];
    const float* b_hh     = (const float*)d_in[9];
    const float* W1       = (const float*)d_in[10];
    const float* b1       = (const float*)d_in[11];
    const float* W2       = (const float*)d_in[12];
    const float* b2       = (const float*)d_in[13];
    const float* w3       = (const float*)d_in[14];
    const float* Wt       = (const float*)d_in[15];
    const float* bt       = (const float*)d_in[16];
    const float* gamma    = (const float*)d_in[17];
    const float* beta     = (const float*)d_in[18];
    float* out = (float*)d_out;

    float *px, *pm, *pagg, *pgt, *pgi, *pgh, *phid, *pa;
    __nv_bfloat16 *pe3, *pa3;
    cudaGetSymbolAddress((void**)&px,   g_x);
    cudaGetSymbolAddress((void**)&pm,   g_m);
    cudaGetSymbolAddress((void**)&pagg, g_agg);
    cudaGetSymbolAddress((void**)&pgt,  g_gt);
    cudaGetSymbolAddress((void**)&pgi,  g_gi);
    cudaGetSymbolAddress((void**)&pgh,  g_gh);
    cudaGetSymbolAddress((void**)&phid, g_hidden);
    cudaGetSymbolAddress((void**)&pa,   g_av);
    cudaGetSymbolAddress((void**)&pe3,  g_e3);
    cudaGetSymbolAddress((void**)&pa3,  g_a3);

    cudaFuncSetAttribute(gemm_tn128, cudaFuncAttributeMaxDynamicSharedMemorySize, SMEM_BYTES);
    cudaFuncSetAttribute(scores_mma_k, cudaFuncAttributeMaxDynamicSharedMemorySize, TCS_SMEM);

    // 0) split embedding[1:] into K=384 [hi|hi|lo] (independent of pipeline)
    int ne = (V_-1)*H_;
    split3_bf16_k<<<(ne + 255)/256, 256>>>(emb + H_, pe3, ne, 0);
    // 1) G^T for x @ G
    transpose128_k<<<64, 256>>>(ggnn_w, pgt);
    // 2) x = embedding[items]
    gather_x_k<<<NN_, 128>>>(items, emb, px);
    // 3) m = x @ G
    gemm_tn128<<<dim3(1, NN_/128), 256, SMEM_BYTES>>>(px, pgt, nullptr, pm, NN_, H_);
    // 4) agg = segment_sum(m[src], dst)
    segsum_k<<<B_, 128>>>(pm, edge, pagg);
    // 5) gi / gh
    gemm_tn128<<<dim3(3, NN_/128), 256, SMEM_BYTES>>>(pagg, W_ih, b_ih, pgi, NN_, 3*H_);
    gemm_tn128<<<dim3(3, NN_/128), 256, SMEM_BYTES>>>(px,   W_hh, b_hh, pgh, NN_, 3*H_);
    // 6) GRU gate update
    gru_update_k<<<NN_*H_/256, 256>>>(pgi, pgh, px);
    // 7) hidden
    build_hidden_k<<<B_*L_, 128>>>(sequence, items, px, emb, phid);
    // 8) attention + hybrid + layernorm -> a[512,128]
    attention_k<<<B_, 128>>>(phid, mask, W1, b1, W2, b2, w3, Wt, bt, gamma, beta, pa);
    // 9) split a into [hi|lo|hi], then tensor-core scores = a @ embedding[1:]^T
    split3_bf16_k<<<(B_*H_ + 255)/256, 256>>>(pa, pa3, B_*H_, 1);
    scores_mma_k<<<dim3((V_ - 1 + 127)/128, B_/128), 256, TCS_SMEM>>>(pa3, pe3, out, V_ - 1);
}

// round 11
// speedup vs baseline: 1.0626x; 1.0626x over previous
#include <cuda_runtime.h>
#include <cuda_bf16.h>
#include <cstdint>
#include <math.h>

#define B_   512
#define L_   20
#define NS_  16
#define EPS_ 32
#define H_   128
#define V_   100000
#define NN_  (B_*NS_)   // 8192 nodes

#define SSTRIDE 130
#define SMEM_BYTES (2 * 128 * SSTRIDE * 4)

// ---------------- device scratch (no runtime allocation allowed) ----------------
__device__ float g_x[NN_*H_];
__device__ float g_m[NN_*H_];
__device__ float g_agg[NN_*H_];
__device__ float g_gt[H_*H_];
__device__ float g_gi[NN_*3*H_];
__device__ float g_gh[NN_*3*H_];
__device__ float g_hidden[B_*L_*H_];
__device__ float g_av[B_*H_];
// K=384 three-segment bf16 splits: A3=[hi|lo|hi], B3=[hi|hi|lo]
// => dot = hi*hi + lo*hi + hi*lo  (missing only lo*lo ~ 2^-18)
__device__ __nv_bfloat16 g_e3[(V_-1)*384];
__device__ __nv_bfloat16 g_a3[B_*384];

// packed fp32x2 FMA
#define FMA2(acc, a, b) asm("fma.rn.f32x2 %0, %1, %2, %0;" : "+l"(acc) : "l"(a), "l"(b))

// =================================================================================
// SIMT fp32 GEMM (middle ops): C[M,N] = A[M,128]*B[N,128]^T (+bias)
// =================================================================================
__global__ void __launch_bounds__(256, 1) gemm_tn128(
    const float* __restrict__ A, const float* __restrict__ B,
    const float* __restrict__ bias, float* __restrict__ C, int M, int N)
{
    extern __shared__ __align__(16) float smem[];
    float* As = smem;
    float* Bs = smem + 128*SSTRIDE;

    const int tid = threadIdx.x;
    const int m0 = blockIdx.y << 7;
    const int n0 = blockIdx.x << 7;

    {
        const float4* A4 = reinterpret_cast<const float4*>(A);
        const float4* B4 = reinterpret_cast<const float4*>(B);
#pragma unroll
        for (int i = tid; i < 128*32; i += 256) {
            int r = i >> 5, c = i & 31;
            float4 va = A4[(m0 + r)*32 + c];
            float2* pa = reinterpret_cast<float2*>(&As[r*SSTRIDE + 4*c]);
            pa[0] = make_float2(va.x, va.y);
            pa[1] = make_float2(va.z, va.w);
            int gr = n0 + r; gr = (gr < N) ? gr : (N - 1);
            float4 vb = B4[gr*32 + c];
            float2* pb = reinterpret_cast<float2*>(&Bs[r*SSTRIDE + 4*c]);
            pb[0] = make_float2(vb.x, vb.y);
            pb[1] = make_float2(vb.z, vb.w);
        }
    }
    __syncthreads();

    const int tx = tid & 15, ty = tid >> 4;
    unsigned long long acc[8][8];
#pragma unroll
    for (int i = 0; i < 8; i++)
#pragma unroll
        for (int j = 0; j < 8; j++) acc[i][j] = 0ull;

#pragma unroll 8
    for (int t = 0; t < 64; ++t) {
        unsigned long long a2[8], b2[8];
#pragma unroll
        for (int i = 0; i < 8; i++) {
            a2[i] = *reinterpret_cast<const unsigned long long*>(&As[(16*i + ty)*SSTRIDE + 2*t]);
            b2[i] = *reinterpret_cast<const unsigned long long*>(&Bs[(16*i + tx)*SSTRIDE + 2*t]);
        }
#pragma unroll
        for (int i = 0; i < 8; i++)
#pragma unroll
            for (int j = 0; j < 8; j++)
                FMA2(acc[i][j], a2[i], b2[j]);
    }

#pragma unroll
    for (int i = 0; i < 8; i++) {
        int row = m0 + ty + 16*i;
#pragma unroll
        for (int j = 0; j < 8; j++) {
            int col = n0 + tx + 16*j;
            if (col < N) {
                float2 p = *reinterpret_cast<float2*>(&acc[i][j]);
                float v = p.x + p.y;
                if (bias) v += bias[col];
                C[row * N + col] = v;
            }
        }
    }
}

// =================================================================================
// mma.sync bf16 scores GEMM: C[M,N] = A3[M,384] * B3[N,384]^T  (fp32 accum)
// cp.async 3-stage K-pipeline: 3 chunks of K=128 prefetched as commit groups,
// compute of chunk c overlaps loads of c+1, c+2.
// 128x128 tile/CTA, 256 thr, 8 warps (2m x 4n), warp tile 64x32, m16n8k16.
// Chunk rows 128 bf16 + 8 pad = 272B (bank stride 4 -> ldmatrix conflict-free).
// Grid is (Mblocks=4, Nblocks): adjacent CTAs share the B tile via L2.
// NOTE: N is odd (99999) -> epilogue must use scalar 32-bit stores only.
// =================================================================================
#define CROW   136                      // chunk row stride in bf16 (272 B)
#define CTILE  (128*CROW*2)             // one 128x128 bf16 chunk tile = 34816 B
#define TCS_SMEM (6*CTILE)              // A0 B0 A1 B1 A2 B2 = 208896 B

__device__ __forceinline__ uint32_t smem_u32(const void* p) {
    uint32_t a;
    asm("{ .reg .u64 t; cvta.to.shared.u64 t, %1; cvt.u32.u64 %0, t; }" : "=r"(a) : "l"(p));
    return a;
}
#define CPASYNC16(dst, src) \
    asm volatile("cp.async.cg.shared.global [%0], [%1], 16;" :: "r"(dst), "l"(src))
#define CPCOMMIT() asm volatile("cp.async.commit_group;" ::: "memory")
#define CPWAIT(n)  asm volatile("cp.async.wait_group " #n ";" ::: "memory")
#define LDSM4(r0,r1,r2,r3,addr) \
    asm volatile("ldmatrix.sync.aligned.m8n8.x4.shared.b16 {%0,%1,%2,%3}, [%4];" \
        : "=r"(r0), "=r"(r1), "=r"(r2), "=r"(r3) : "r"(addr))
#define MMA16816(c, a, b0, b1) \
    asm volatile("mma.sync.aligned.m16n8k16.row.col.f32.bf16.bf16.f32 " \
        "{%0,%1,%2,%3}, {%4,%5,%6,%7}, {%8,%9}, {%0,%1,%2,%3};" \
        : "+f"((c)[0]), "+f"((c)[1]), "+f"((c)[2]), "+f"((c)[3]) \
        : "r"((a)[0]), "r"((a)[1]), "r"((a)[2]), "r"((a)[3]), "r"(b0), "r"(b1))

__global__ void __launch_bounds__(256, 1) scores_mma_k(
    const __nv_bfloat16* __restrict__ A3, const __nv_bfloat16* __restrict__ B3,
    float* __restrict__ C, int N)
{
    extern __shared__ __align__(16) __nv_bfloat16 smemb[];
    const int tid = threadIdx.x;
    const int m0 = blockIdx.x << 7;          // 4 m-blocks (fast dim -> share B via L2)
    const int n0 = blockIdx.y << 7;

    // Prefetch all 3 K-chunks (A then B per chunk), one commit group per chunk.
    {
        const char* Ab = reinterpret_cast<const char*>(A3);
        const char* Bb = reinterpret_cast<const char*>(B3);
#pragma unroll
        for (int c = 0; c < 3; c++) {
            uint32_t sA = smem_u32(smemb) + c*2*CTILE;
            uint32_t sB = sA + CTILE;
#pragma unroll
            for (int j = 0; j < 8; j++) {
                int idx = tid + j*256;       // 2048 chunks of 16B per tile
                int r = idx >> 4, ch = idx & 15;
                long gofA = ((long)(m0 + r)*48 + c*16 + ch) * 16;
                CPASYNC16(sA + r*272 + ch*16, Ab + gofA);
                int gr = n0 + r; gr = (gr < N) ? gr : (N - 1);
                long gofB = ((long)gr*48 + c*16 + ch) * 16;
                CPASYNC16(sB + r*272 + ch*16, Bb + gofB);
            }
            CPCOMMIT();
        }
    }

    const int lane = tid & 31, wid = tid >> 5;
    const int wm = wid >> 2, wn = wid & 3;   // warp tile: rows wm*64, cols wn*32

    // ldmatrix lane offsets within a chunk tile (bytes)
    uint32_t a_off[4], b_off[2];
#pragma unroll
    for (int mi = 0; mi < 4; mi++) {
        int arow = wm*64 + mi*16 + (lane & 15);
        int acol = (lane >> 4) * 8;
        a_off[mi] = arow*272 + acol*2;
    }
#pragma unroll
    for (int njp = 0; njp < 2; njp++) {
        int brow = wn*32 + njp*16 + ((lane >> 4) & 1)*8 + (lane & 7);
        int bcol = ((lane >> 3) & 1) * 8;
        b_off[njp] = brow*272 + bcol*2;
    }

    float acc[4][4][4];
#pragma unroll
    for (int i = 0; i < 4; i++)
#pragma unroll
        for (int j = 0; j < 4; j++)
#pragma unroll
            for (int q = 0; q < 4; q++) acc[i][j][q] = 0.f;

#pragma unroll
    for (int c = 0; c < 3; c++) {
        if (c == 0)      { CPWAIT(2); }
        else if (c == 1) { CPWAIT(1); }
        else             { CPWAIT(0); }
        __syncthreads();
        uint32_t baseA = smem_u32(smemb) + c*2*CTILE;
        uint32_t baseB = baseA + CTILE;
#pragma unroll
        for (int k = 0; k < 8; k++) {        // 8 k16-steps per 128-chunk
            uint32_t a[4][4], b[2][4];
#pragma unroll
            for (int mi = 0; mi < 4; mi++)
                LDSM4(a[mi][0], a[mi][1], a[mi][2], a[mi][3], baseA + a_off[mi] + k*32);
#pragma unroll
            for (int njp = 0; njp < 2; njp++)
                LDSM4(b[njp][0], b[njp][1], b[njp][2], b[njp][3], baseB + b_off[njp] + k*32);
#pragma unroll
            for (int mi = 0; mi < 4; mi++)
#pragma unroll
                for (int nj = 0; nj < 4; nj++)
                    MMA16816(acc[mi][nj], a[mi],
                             b[nj >> 1][(nj & 1)*2], b[nj >> 1][(nj & 1)*2 + 1]);
        }
    }

    // Epilogue: scalar fp32 stores only (N odd -> no 8B alignment guarantee).
#pragma unroll
    for (int mi = 0; mi < 4; mi++) {
        int r0 = m0 + wm*64 + mi*16 + (lane >> 2);
        long base0 = (long)r0 * N;
        long base1 = (long)(r0 + 8) * N;
#pragma unroll
        for (int nj = 0; nj < 4; nj++) {
            int c0 = n0 + wn*32 + nj*8 + (lane & 3)*2;
            if (c0 < N) {
                C[base0 + c0] = acc[mi][nj][0];
                C[base1 + c0] = acc[mi][nj][2];
                if (c0 + 1 < N) {
                    C[base0 + c0 + 1] = acc[mi][nj][1];
                    C[base1 + c0 + 1] = acc[mi][nj][3];
                }
            }
        }
    }
}

// ---------------- small kernels ----------------

// fp32 [n x 128] -> bf16 [n x 384]; mode 0 (B/emb): [hi|hi|lo], mode 1 (A): [hi|lo|hi]
__global__ void split3_bf16_k(const float* __restrict__ src, __nv_bfloat16* __restrict__ dst,
                              int n, int mode) {
    int i = blockIdx.x * 256 + threadIdx.x;
    if (i < n) {
        int row = i >> 7, col = i & 127;
        float v = src[i];
        __nv_bfloat16 h = __float2bfloat16(v);
        __nv_bfloat16 l = __float2bfloat16(v - __bfloat162float(h));
        __nv_bfloat16* d = dst + row*384 + col;
        if (mode == 0) { d[0] = h; d[128] = h; d[256] = l; }
        else           { d[0] = h; d[128] = l; d[256] = h; }
    }
}

__global__ void transpose128_k(const float* __restrict__ G, float* __restrict__ GT) {
    int i = blockIdx.x * 256 + threadIdx.x;
    int k = i >> 7, j = i & 127;
    GT[j*128 + k] = G[i];
}

__global__ void gather_x_k(const int* __restrict__ items, const float* __restrict__ emb,
                           float* __restrict__ x) {
    int n = blockIdx.x, t = threadIdx.x;
    x[n*H_ + t] = emb[items[n]*H_ + t];
}

__global__ void segsum_k(const float* __restrict__ m, const int* __restrict__ ei,
                         float* __restrict__ agg) {
    __shared__ float ms[NS_][H_];
    __shared__ float as[NS_][H_];
    int b = blockIdx.x, t = threadIdx.x;
#pragma unroll
    for (int j = 0; j < NS_; j++) { ms[j][t] = m[(b*NS_ + j)*H_ + t]; as[j][t] = 0.f; }
    __syncthreads();
    const int* src = ei + b*EPS_;
    const int* dst = ei + B_*EPS_ + b*EPS_;
#pragma unroll
    for (int e = 0; e < EPS_; e++) {
        int s = src[e] - b*NS_;
        int d = dst[e] - b*NS_;
        as[d][t] += ms[s][t];
    }
#pragma unroll
    for (int j = 0; j < NS_; j++) agg[(b*NS_ + j)*H_ + t] = as[j][t];
}

__global__ void gru_update_k(const float* __restrict__ gi, const float* __restrict__ gh,
                             float* __restrict__ x) {
    int i = blockIdx.x * 256 + threadIdx.x;
    int n = i >> 7, h = i & 127;
    const float* gin = gi + n*3*H_;
    const float* ghn = gh + n*3*H_;
    float ir = gin[h], iz = gin[H_ + h], in_ = gin[2*H_ + h];
    float hr = ghn[h], hz = ghn[H_ + h], hn  = ghn[2*H_ + h];
    float r = 1.f / (1.f + expf(-(ir + hr)));
    float z = 1.f / (1.f + expf(-(iz + hz)));
    float nn = tanhf(in_ + r*hn);
    x[i] = (1.f - z)*nn + z*x[i];
}

__global__ void build_hidden_k(const int* __restrict__ seq, const int* __restrict__ items,
                               const float* __restrict__ x, const float* __restrict__ emb,
                               float* __restrict__ hid) {
    int bl = blockIdx.x;
    int b = bl / L_, t = threadIdx.x;
    int s = seq[bl];
    float v = 0.f;
    if (s != 0) {
        int j = -1;
#pragma unroll
        for (int q = 0; q < NS_; q++) if (j < 0 && items[b*NS_ + q] == s) j = q;
        v = (j >= 0) ? x[(b*NS_ + j)*H_ + t] : emb[s*H_ + t];
    }
    hid[bl*H_ + t] = v;
}

__device__ __forceinline__ float bsum128(float v, float* s4) {
#pragma unroll
    for (int o = 16; o > 0; o >>= 1) v += __shfl_xor_sync(0xffffffffu, v, o);
    int w = threadIdx.x >> 5;
    if ((threadIdx.x & 31) == 0) s4[w] = v;
    __syncthreads();
    v = s4[0] + s4[1] + s4[2] + s4[3];
    __syncthreads();
    return v;
}

__global__ void attention_k(const float* __restrict__ hid_g, const int* __restrict__ mask,
                            const float* __restrict__ W1, const float* __restrict__ b1,
                            const float* __restrict__ W2, const float* __restrict__ b2,
                            const float* __restrict__ w3, const float* __restrict__ Wt,
                            const float* __restrict__ bt, const float* __restrict__ gamma,
                            const float* __restrict__ beta, float* __restrict__ outA)
{
    __shared__ float hid[L_][H_];
    __shared__ float a_sh[H_];
    __shared__ float red[4];
    int b = blockIdx.x, t = threadIdx.x;
#pragma unroll
    for (int l = 0; l < L_; l++) hid[l][t] = hid_g[(b*L_ + l)*H_ + t];
    int len = 0;
#pragma unroll
    for (int l = 0; l < L_; l++) len += mask[b*L_ + l];
    __syncthreads();

    const float* ht = hid[len - 1];
    float q1 = b1[t];
#pragma unroll 8
    for (int k = 0; k < H_; k++) q1 += W1[t*H_ + k] * ht[k];
    float w3t = w3[t];

    float acc = 0.f;
    for (int l = 0; l < L_; l++) {
        float q2 = b2[t];
#pragma unroll 8
        for (int k = 0; k < H_; k++) q2 += W2[t*H_ + k] * hid[l][k];
        float v = (1.f / (1.f + expf(-(q1 + q2)))) * w3t;
        float alpha = bsum128(v, red);
        acc += alpha * hid[l][t] * (float)mask[b*L_ + l];
    }
    a_sh[t] = acc;
    __syncthreads();

    float o = bt[t];
#pragma unroll 8
    for (int k = 0; k < H_; k++) o += Wt[t*2*H_ + k] * a_sh[k];
#pragma unroll 8
    for (int k = 0; k < H_; k++) o += Wt[t*2*H_ + H_ + k] * ht[k];

    float mu = bsum128(o, red) * (1.f / H_);
    float d = o - mu;
    float var = bsum128(d*d, red) * (1.f / H_);
    outA[b*H_ + t] = d * rsqrtf(var + 1e-5f) * gamma[t] + beta[t];
}

// =================================================================================
extern "C" void kernel_launch(void* const* d_in, const int* in_sizes, int n_in,
                              void* d_out, int out_size)
{
    const int*   items    = (const int*)d_in[0];
    const int*   edge     = (const int*)d_in[1];
    const int*   sequence = (const int*)d_in[2];
    const int*   mask     = (const int*)d_in[3];
    const float* emb      = (const float*)d_in[4];
    const float* ggnn_w   = (const float*)d_in[5];
    const float* W_ih     = (const float*)d_in[6];
    const float* W_hh     = (const float*)d_in[7];
    const float* b_ih     = (const float*)d_in[8];
    const float* b_hh     = (const float*)d_in[9];
    const float* W1       = (const float*)d_in[10];
    const float* b1       = (const float*)d_in[11];
    const float* W2       = (const float*)d_in[12];
    const float* b2       = (const float*)d_in[13];
    const float* w3       = (const float*)d_in[14];
    const float* Wt       = (const float*)d_in[15];
    const float* bt       = (const float*)d_in[16];
    const float* gamma    = (const float*)d_in[17];
    const float* beta     = (const float*)d_in[18];
    float* out = (float*)d_out;

    float *px, *pm, *pagg, *pgt, *pgi, *pgh, *phid, *pa;
    __nv_bfloat16 *pe3, *pa3;
    cudaGetSymbolAddress((void**)&px,   g_x);
    cudaGetSymbolAddress((void**)&pm,   g_m);
    cudaGetSymbolAddress((void**)&pagg, g_agg);
    cudaGetSymbolAddress((void**)&pgt,  g_gt);
    cudaGetSymbolAddress((void**)&pgi,  g_gi);
    cudaGetSymbolAddress((void**)&pgh,  g_gh);
    cudaGetSymbolAddress((void**)&phid, g_hidden);
    cudaGetSymbolAddress((void**)&pa,   g_av);
    cudaGetSymbolAddress((void**)&pe3,  g_e3);
    cudaGetSymbolAddress((void**)&pa3,  g_a3);

    cudaFuncSetAttribute(gemm_tn128, cudaFuncAttributeMaxDynamicSharedMemorySize, SMEM_BYTES);
    cudaFuncSetAttribute(scores_mma_k, cudaFuncAttributeMaxDynamicSharedMemorySize, TCS_SMEM);

    // 0) split embedding[1:] into K=384 [hi|hi|lo] (independent of pipeline)
    int ne = (V_-1)*H_;
    split3_bf16_k<<<(ne + 255)/256, 256>>>(emb + H_, pe3, ne, 0);
    // 1) G^T for x @ G
    transpose128_k<<<64, 256>>>(ggnn_w, pgt);
    // 2) x = embedding[items]
    gather_x_k<<<NN_, 128>>>(items, emb, px);
    // 3) m = x @ G
    gemm_tn128<<<dim3(1, NN_/128), 256, SMEM_BYTES>>>(px, pgt, nullptr, pm, NN_, H_);
    // 4) agg = segment_sum(m[src], dst)
    segsum_k<<<B_, 128>>>(pm, edge, pagg);
    // 5) gi / gh
    gemm_tn128<<<dim3(3, NN_/128), 256, SMEM_BYTES>>>(pagg, W_ih, b_ih, pgi, NN_, 3*H_);
    gemm_tn128<<<dim3(3, NN_/128), 256, SMEM_BYTES>>>(px,   W_hh, b_hh, pgh, NN_, 3*H_);
    // 6) GRU gate update
    gru_update_k<<<NN_*H_/256, 256>>>(pgi, pgh, px);
    // 7) hidden
    build_hidden_k<<<B_*L_, 128>>>(sequence, items, px, emb, phid);
    // 8) attention + hybrid + layernorm -> a[512,128]
    attention_k<<<B_, 128>>>(phid, mask, W1, b1, W2, b2, w3, Wt, bt, gamma, beta, pa);
    // 9) split a into [hi|lo|hi], then tensor-core scores = a @ embedding[1:]^T
    //    grid: x = 4 m-blocks (fast) so CTAs sharing a B tile are co-resident.
    split3_bf16_k<<<(B_*H_ + 255)/256, 256>>>(pa, pa3, B_*H_, 1);
    scores_mma_k<<<dim3(B_/128, (V_ - 1 + 127)/128), 256, TCS_SMEM>>>(pa3, pe3, out, V_ - 1);
}

// round 13
// speedup vs baseline: 3.0956x; 2.9131x over previous
#include <cuda_runtime.h>
#include <cuda_bf16.h>
#include <cstdint>
#include <math.h>

#define B_   512
#define L_   20
#define NS_  16
#define EPS_ 32
#define H_   128
#define V_   100000
#define NN_  (B_*NS_)

// ---------------- device scratch (no runtime allocation allowed) ----------------
// K=384 three-segment bf16 splits: A3=[hi|lo|hi], B3=[hi|hi|lo]
// => dot = hi*hi + lo*hi + hi*lo (missing only lo*lo ~ 2^-18)
__device__ __nv_bfloat16 g_e3[(V_-1)*384];
__device__ __nv_bfloat16 g_a3[B_*384];
// transposed weights: WihT[128][384] WhhT[128][384] W1T[128][128] W2T[128][128] WtT[256][128]
#define OW_IH 0
#define OW_HH 49152
#define OW_1  98304
#define OW_2  114688
#define OW_T  131072
#define WT_TOTAL 163840
__device__ float g_wt[WT_TOTAL];

// =================================================================================
// mma.sync bf16 scores GEMM (UNCHANGED from R11): C[M,N] = A3[M,384]*B3[N,384]^T
// =================================================================================
#define CROW   136
#define CTILE  (128*CROW*2)
#define TCS_SMEM (6*CTILE)

__device__ __forceinline__ uint32_t smem_u32(const void* p) {
    uint32_t a;
    asm("{ .reg .u64 t; cvta.to.shared.u64 t, %1; cvt.u32.u64 %0, t; }" : "=r"(a) : "l"(p));
    return a;
}
#define CPASYNC16(dst, src) \
    asm volatile("cp.async.cg.shared.global [%0], [%1], 16;" :: "r"(dst), "l"(src))
#define CPCOMMIT() asm volatile("cp.async.commit_group;" ::: "memory")
#define CPWAIT(n)  asm volatile("cp.async.wait_group " #n ";" ::: "memory")
#define LDSM4(r0,r1,r2,r3,addr) \
    asm volatile("ldmatrix.sync.aligned.m8n8.x4.shared.b16 {%0,%1,%2,%3}, [%4];" \
        : "=r"(r0), "=r"(r1), "=r"(r2), "=r"(r3) : "r"(addr))
#define MMA16816(c, a, b0, b1) \
    asm volatile("mma.sync.aligned.m16n8k16.row.col.f32.bf16.bf16.f32 " \
        "{%0,%1,%2,%3}, {%4,%5,%6,%7}, {%8,%9}, {%0,%1,%2,%3};" \
        : "+f"((c)[0]), "+f"((c)[1]), "+f"((c)[2]), "+f"((c)[3]) \
        : "r"((a)[0]), "r"((a)[1]), "r"((a)[2]), "r"((a)[3]), "r"(b0), "r"(b1))

__global__ void __launch_bounds__(256, 1) scores_mma_k(
    const __nv_bfloat16* __restrict__ A3, const __nv_bfloat16* __restrict__ B3,
    float* __restrict__ C, int N)
{
    extern __shared__ __align__(16) __nv_bfloat16 smemb[];
    const int tid = threadIdx.x;
    const int m0 = blockIdx.x << 7;
    const int n0 = blockIdx.y << 7;

    {
        const char* Ab = reinterpret_cast<const char*>(A3);
        const char* Bb = reinterpret_cast<const char*>(B3);
#pragma unroll
        for (int c = 0; c < 3; c++) {
            uint32_t sA = smem_u32(smemb) + c*2*CTILE;
            uint32_t sB = sA + CTILE;
#pragma unroll
            for (int j = 0; j < 8; j++) {
                int idx = tid + j*256;
                int r = idx >> 4, ch = idx & 15;
                long gofA = ((long)(m0 + r)*48 + c*16 + ch) * 16;
                CPASYNC16(sA + r*272 + ch*16, Ab + gofA);
                int gr = n0 + r; gr = (gr < N) ? gr : (N - 1);
                long gofB = ((long)gr*48 + c*16 + ch) * 16;
                CPASYNC16(sB + r*272 + ch*16, Bb + gofB);
            }
            CPCOMMIT();
        }
    }

    const int lane = tid & 31, wid = tid >> 5;
    const int wm = wid >> 2, wn = wid & 3;

    uint32_t a_off[4], b_off[2];
#pragma unroll
    for (int mi = 0; mi < 4; mi++) {
        int arow = wm*64 + mi*16 + (lane & 15);
        int acol = (lane >> 4) * 8;
        a_off[mi] = arow*272 + acol*2;
    }
#pragma unroll
    for (int njp = 0; njp < 2; njp++) {
        int brow = wn*32 + njp*16 + ((lane >> 4) & 1)*8 + (lane & 7);
        int bcol = ((lane >> 3) & 1) * 8;
        b_off[njp] = brow*272 + bcol*2;
    }

    float acc[4][4][4];
#pragma unroll
    for (int i = 0; i < 4; i++)
#pragma unroll
        for (int j = 0; j < 4; j++)
#pragma unroll
            for (int q = 0; q < 4; q++) acc[i][j][q] = 0.f;

#pragma unroll
    for (int c = 0; c < 3; c++) {
        if (c == 0)      { CPWAIT(2); }
        else if (c == 1) { CPWAIT(1); }
        else             { CPWAIT(0); }
        __syncthreads();
        uint32_t baseA = smem_u32(smemb) + c*2*CTILE;
        uint32_t baseB = baseA + CTILE;
#pragma unroll
        for (int k = 0; k < 8; k++) {
            uint32_t a[4][4], b[2][4];
#pragma unroll
            for (int mi = 0; mi < 4; mi++)
                LDSM4(a[mi][0], a[mi][1], a[mi][2], a[mi][3], baseA + a_off[mi] + k*32);
#pragma unroll
            for (int njp = 0; njp < 2; njp++)
                LDSM4(b[njp][0], b[njp][1], b[njp][2], b[njp][3], baseB + b_off[njp] + k*32);
#pragma unroll
            for (int mi = 0; mi < 4; mi++)
#pragma unroll
                for (int nj = 0; nj < 4; nj++)
                    MMA16816(acc[mi][nj], a[mi],
                             b[nj >> 1][(nj & 1)*2], b[nj >> 1][(nj & 1)*2 + 1]);
        }
    }

#pragma unroll
    for (int mi = 0; mi < 4; mi++) {
        int r0 = m0 + wm*64 + mi*16 + (lane >> 2);
        long base0 = (long)r0 * N;
        long base1 = (long)(r0 + 8) * N;
#pragma unroll
        for (int nj = 0; nj < 4; nj++) {
            int c0 = n0 + wn*32 + nj*8 + (lane & 3)*2;
            if (c0 < N) {
                C[base0 + c0] = acc[mi][nj][0];
                C[base1 + c0] = acc[mi][nj][2];
                if (c0 + 1 < N) {
                    C[base0 + c0 + 1] = acc[mi][nj][1];
                    C[base1 + c0 + 1] = acc[mi][nj][3];
                }
            }
        }
    }
}

// =================================================================================
// split3 for embedding, vectorized: fp32 [n x 128] -> bf16 [n x 384] = [hi|hi|lo]
// =================================================================================
__global__ void split3v_k(const float* __restrict__ src, __nv_bfloat16* __restrict__ dst,
                          int nrows) {
    int i = blockIdx.x * 256 + threadIdx.x;          // nrows*64 pairs
    if (i < nrows * 64) {
        int row = i >> 6, c = (i & 63) * 2;
        float2 v = *reinterpret_cast<const float2*>(src + row*128 + c);
        __nv_bfloat162 hp = __floats2bfloat162_rn(v.x, v.y);
        float lx = v.x - __bfloat162float(hp.x);
        float ly = v.y - __bfloat162float(hp.y);
        __nv_bfloat162 lp = __floats2bfloat162_rn(lx, ly);
        __nv_bfloat16* d = dst + (long)row*384 + c;
        *reinterpret_cast<__nv_bfloat162*>(d)       = hp;
        *reinterpret_cast<__nv_bfloat162*>(d + 128) = hp;
        *reinterpret_cast<__nv_bfloat162*>(d + 256) = lp;
    }
}

// =================================================================================
// prep: transpose weights into g_wt
// =================================================================================
__global__ void prep_t_k(const float* __restrict__ W_ih, const float* __restrict__ W_hh,
                         const float* __restrict__ W1,  const float* __restrict__ W2,
                         const float* __restrict__ Wt,  float* __restrict__ wt) {
    int i = blockIdx.x * 256 + threadIdx.x;
    if (i < OW_HH) {                               // WihT[k*384+j] = W_ih[j*128+k]
        int k = i / 384, j = i % 384;
        wt[i] = W_ih[j*128 + k];
    } else if (i < OW_1) {
        int t = i - OW_HH; int k = t / 384, j = t % 384;
        wt[i] = W_hh[j*128 + k];
    } else if (i < OW_2) {
        int t = i - OW_1; int k = t / 128, j = t % 128;
        wt[i] = W1[j*128 + k];
    } else if (i < OW_T) {
        int t = i - OW_2; int k = t / 128, j = t % 128;
        wt[i] = W2[j*128 + k];
    } else if (i < WT_TOTAL) {
        int t = i - OW_T; int k = t / 128, j = t % 128;   // k in [0,256)
        wt[i] = Wt[j*256 + k];
    }
}

// =================================================================================
// Megakernel: one block per session. Fuses gather + x@G + segsum + GRU + hidden
// + attention + layernorm + split3(a). 128 threads = hidden dim j.
// =================================================================================
__device__ __forceinline__ float bsum128(float v, float* s4) {
#pragma unroll
    for (int o = 16; o > 0; o >>= 1) v += __shfl_xor_sync(0xffffffffu, v, o);
    int w = threadIdx.x >> 5;
    if ((threadIdx.x & 31) == 0) s4[w] = v;
    __syncthreads();
    v = s4[0] + s4[1] + s4[2] + s4[3];
    __syncthreads();
    return v;
}

__global__ void __launch_bounds__(128) mega_k(
    const int* __restrict__ items, const int* __restrict__ edge,
    const int* __restrict__ seq, const int* __restrict__ mask,
    const float* __restrict__ emb, const float* __restrict__ G,
    const float* __restrict__ wt,
    const float* __restrict__ b_ih, const float* __restrict__ b_hh,
    const float* __restrict__ b1, const float* __restrict__ b2,
    const float* __restrict__ w3, const float* __restrict__ bt,
    const float* __restrict__ gamma, const float* __restrict__ beta,
    __nv_bfloat16* __restrict__ a3)
{
    __shared__ float xs[NS_][H_];
    __shared__ float aggs[NS_][H_];
    __shared__ float hid[L_][H_];      // rows 0..15 reused as m before hidden
    __shared__ int items_s[NS_];
    __shared__ float a_sh[H_];
    __shared__ float red[4];

    const int b = blockIdx.x, j = threadIdx.x;
    if (j < NS_) items_s[j] = items[b*NS_ + j];
    __syncthreads();

    // x = embedding[items]
#pragma unroll
    for (int i = 0; i < NS_; i++) xs[i][j] = emb[items_s[i]*H_ + j];
    __syncthreads();

    // m = x @ G  (into hid rows 0..15)
    {
        float mcol[NS_];
#pragma unroll
        for (int i = 0; i < NS_; i++) mcol[i] = 0.f;
#pragma unroll 4
        for (int k = 0; k < H_; k++) {
            float gk = G[k*H_ + j];
#pragma unroll
            for (int i = 0; i < NS_; i++) mcol[i] += xs[i][k] * gk;
        }
#pragma unroll
        for (int i = 0; i < NS_; i++) hid[i][j] = mcol[i];
    }

    // agg = segment_sum(m[src], dst)  (column-local -> race-free)
#pragma unroll
    for (int i = 0; i < NS_; i++) aggs[i][j] = 0.f;
    {
        const int* src = edge + b*EPS_;
        const int* dst = edge + B_*EPS_ + b*EPS_;
#pragma unroll
        for (int e = 0; e < EPS_; e++) {
            int s = src[e] - b*NS_;
            int d = dst[e] - b*NS_;
            aggs[d][j] += hid[s][j];
        }
    }
    __syncthreads();   // gi/gh reads aggs/xs cross-column

    // gi = agg@W_ih^T + b_ih ; gh = x@W_hh^T + b_hh ; GRU update (two halves of 8)
    {
        const float* wih = wt + OW_IH;
        const float* whh = wt + OW_HH;
        float bi0 = b_ih[j], bi1 = b_ih[H_ + j], bi2 = b_ih[2*H_ + j];
        float bh0 = b_hh[j], bh1 = b_hh[H_ + j], bh2 = b_hh[2*H_ + j];
#pragma unroll
        for (int half = 0; half < 2; half++) {
            float gi0[8], gi1[8], gi2[8], gh0[8], gh1[8], gh2[8];
#pragma unroll
            for (int i = 0; i < 8; i++) {
                gi0[i] = bi0; gi1[i] = bi1; gi2[i] = bi2;
                gh0[i] = bh0; gh1[i] = bh1; gh2[i] = bh2;
            }
#pragma unroll 2
            for (int k = 0; k < H_; k++) {
                float wi0 = wih[k*384 + j], wi1 = wih[k*384 + H_ + j], wi2 = wih[k*384 + 2*H_ + j];
                float wh0 = whh[k*384 + j], wh1 = whh[k*384 + H_ + j], wh2 = whh[k*384 + 2*H_ + j];
#pragma unroll
                for (int i = 0; i < 8; i++) {
                    float ak = aggs[half*8 + i][k];
                    float xk = xs[half*8 + i][k];
                    gi0[i] += ak*wi0; gi1[i] += ak*wi1; gi2[i] += ak*wi2;
                    gh0[i] += xk*wh0; gh1[i] += xk*wh1; gh2[i] += xk*wh2;
                }
            }
            // RACE FIX: all warps must finish READING xs[half rows][*] before any
            // warp writes the GRU update into those rows.
            __syncthreads();
#pragma unroll
            for (int i = 0; i < 8; i++) {
                float r = 1.f / (1.f + expf(-(gi0[i] + gh0[i])));
                float z = 1.f / (1.f + expf(-(gi1[i] + gh1[i])));
                float n = tanhf(gi2[i] + r*gh2[i]);
                xs[half*8 + i][j] = (1.f - z)*n + z*xs[half*8 + i][j];
            }
        }
    }

    // hidden[b,l] = matched node feature / embedding fallback / 0  (column-local)
#pragma unroll
    for (int l = 0; l < L_; l++) {
        int s = seq[b*L_ + l];
        float v = 0.f;
        if (s != 0) {
            int idx = -1;
#pragma unroll
            for (int q = 0; q < NS_; q++) if (idx < 0 && items_s[q] == s) idx = q;
            v = (idx >= 0) ? xs[idx][j] : emb[s*H_ + j];
        }
        hid[l][j] = v;
    }
    int len = 0;
#pragma unroll
    for (int l = 0; l < L_; l++) len += mask[b*L_ + l];
    __syncthreads();   // attention reads hid cross-column

    // attention + hybrid + layernorm
    {
        const float* w1t = wt + OW_1;
        const float* w2t = wt + OW_2;
        const float* wtt = wt + OW_T;
        const float* ht = hid[len - 1];
        float q1 = b1[j];
#pragma unroll 8
        for (int k = 0; k < H_; k++) q1 += ht[k] * w1t[k*H_ + j];
        float w3j = w3[j];
        float bb2 = b2[j];

        float acc = 0.f;
        for (int l = 0; l < L_; l++) {
            float q2 = bb2;
#pragma unroll 8
            for (int k = 0; k < H_; k++) q2 += hid[l][k] * w2t[k*H_ + j];
            float v = (1.f / (1.f + expf(-(q1 + q2)))) * w3j;
            float alpha = bsum128(v, red);
            acc += alpha * hid[l][j] * (float)mask[b*L_ + l];
        }
        a_sh[j] = acc;
        __syncthreads();

        float o = bt[j];
#pragma unroll 8
        for (int k = 0; k < H_; k++) o += a_sh[k] * wtt[k*H_ + j];
#pragma unroll 8
        for (int k = 0; k < H_; k++) o += ht[k] * wtt[(H_ + k)*H_ + j];

        float mu = bsum128(o, red) * (1.f / H_);
        float d = o - mu;
        float var = bsum128(d*d, red) * (1.f / H_);
        float aout = d * rsqrtf(var + 1e-5f) * gamma[j] + beta[j];

        // split3 epilogue: A layout [hi|lo|hi]
        __nv_bfloat16 h = __float2bfloat16(aout);
        __nv_bfloat16 lo = __float2bfloat16(aout - __bfloat162float(h));
        a3[b*384 + j]        = h;
        a3[b*384 + H_ + j]   = lo;
        a3[b*384 + 2*H_ + j] = h;
    }
}

// =================================================================================
extern "C" void kernel_launch(void* const* d_in, const int* in_sizes, int n_in,
                              void* d_out, int out_size)
{
    const int*   items    = (const int*)d_in[0];
    const int*   edge     = (const int*)d_in[1];
    const int*   sequence = (const int*)d_in[2];
    const int*   mask     = (const int*)d_in[3];
    const float* emb      = (const float*)d_in[4];
    const float* ggnn_w   = (const float*)d_in[5];
    const float* W_ih     = (const float*)d_in[6];
    const float* W_hh     = (const float*)d_in[7];
    const float* b_ih     = (const float*)d_in[8];
    const float* b_hh     = (const float*)d_in[9];
    const float* W1       = (const float*)d_in[10];
    const float* b1       = (const float*)d_in[11];
    const float* W2       = (const float*)d_in[12];
    const float* b2       = (const float*)d_in[13];
    const float* w3       = (const float*)d_in[14];
    const float* Wt       = (const float*)d_in[15];
    const float* bt       = (const float*)d_in[16];
    const float* gamma    = (const float*)d_in[17];
    const float* beta     = (const float*)d_in[18];
    float* out = (float*)d_out;

    __nv_bfloat16 *pe3, *pa3;
    float* pwt;
    cudaGetSymbolAddress((void**)&pe3, g_e3);
    cudaGetSymbolAddress((void**)&pa3, g_a3);
    cudaGetSymbolAddress((void**)&pwt, g_wt);

    cudaFuncSetAttribute(scores_mma_k, cudaFuncAttributeMaxDynamicSharedMemorySize, TCS_SMEM);

    // 1) split embedding[1:] into K=384 [hi|hi|lo]
    split3v_k<<<((V_-1)*64 + 255)/256, 256>>>(emb + H_, pe3, V_ - 1);
    // 2) transpose weights
    prep_t_k<<<(WT_TOTAL + 255)/256, 256>>>(W_ih, W_hh, W1, W2, Wt, pwt);
    // 3) fused per-session pipeline -> a3[512,384]
    mega_k<<<B_, 128>>>(items, edge, sequence, mask, emb, ggnn_w, pwt,
                        b_ih, b_hh, b1, b2, w3, bt, gamma, beta, pa3);
    // 4) tensor-core scores = a @ embedding[1:]^T   (ncu -s 3 captures THIS launch)
    scores_mma_k<<<dim3(B_/128, (V_ - 1 + 127)/128), 256, TCS_SMEM>>>(pa3, pe3, out, V_ - 1);
}

// round 14
// speedup vs baseline: 3.5626x; 1.1508x over previous
#include <cuda_runtime.h>
#include <cuda_bf16.h>
#include <cstdint>
#include <math.h>

#define B_   512
#define L_   20
#define NS_  16
#define EPS_ 32
#define H_   128
#define V_   100000
#define NN_  (B_*NS_)

// ---------------- device scratch (no runtime allocation allowed) ----------------
// K=384 three-segment bf16 splits: A3=[hi|lo|hi], B3=[hi|hi|lo]
// => dot = hi*hi + lo*hi + hi*lo (missing only lo*lo ~ 2^-18)
__device__ __nv_bfloat16 g_e3[(V_-1)*384];
__device__ __nv_bfloat16 g_a3[B_*384];
// transposed weights: WihT[128][384] WhhT[128][384] W1T[128][128] W2T[128][128] WtT[256][128]
#define OW_IH 0
#define OW_HH 49152
#define OW_1  98304
#define OW_2  114688
#define OW_T  131072
#define WT_TOTAL 163840
__device__ float g_wt[WT_TOTAL];

// =================================================================================
// mma.sync bf16 scores GEMM: C[M,N] = A3[M,384]*B3[N,384]^T  (fp32 accum)
// 128x128 tile/CTA, 512 thr / 16 warps (4m x 4n), warp tile 32x32, m16n8k16.
// cp.async 3-chunk K-pipeline; epilogue staged through smem for coalesced stores.
// =================================================================================
#define CROW   136
#define CTILE  (128*CROW*2)
#define TCS_SMEM (6*CTILE)

__device__ __forceinline__ uint32_t smem_u32(const void* p) {
    uint32_t a;
    asm("{ .reg .u64 t; cvta.to.shared.u64 t, %1; cvt.u32.u64 %0, t; }" : "=r"(a) : "l"(p));
    return a;
}
#define CPASYNC16(dst, src) \
    asm volatile("cp.async.cg.shared.global [%0], [%1], 16;" :: "r"(dst), "l"(src))
#define CPCOMMIT() asm volatile("cp.async.commit_group;" ::: "memory")
#define CPWAIT(n)  asm volatile("cp.async.wait_group " #n ";" ::: "memory")
#define LDSM4(r0,r1,r2,r3,addr) \
    asm volatile("ldmatrix.sync.aligned.m8n8.x4.shared.b16 {%0,%1,%2,%3}, [%4];" \
        : "=r"(r0), "=r"(r1), "=r"(r2), "=r"(r3) : "r"(addr))
#define MMA16816(c, a, b0, b1) \
    asm volatile("mma.sync.aligned.m16n8k16.row.col.f32.bf16.bf16.f32 " \
        "{%0,%1,%2,%3}, {%4,%5,%6,%7}, {%8,%9}, {%0,%1,%2,%3};" \
        : "+f"((c)[0]), "+f"((c)[1]), "+f"((c)[2]), "+f"((c)[3]) \
        : "r"((a)[0]), "r"((a)[1]), "r"((a)[2]), "r"((a)[3]), "r"(b0), "r"(b1))

__global__ void __launch_bounds__(512, 1) scores_mma_k(
    const __nv_bfloat16* __restrict__ A3, const __nv_bfloat16* __restrict__ B3,
    float* __restrict__ C, int N)
{
    extern __shared__ __align__(16) __nv_bfloat16 smemb[];
    const int tid = threadIdx.x;
    const int m0 = blockIdx.x << 7;
    const int n0 = blockIdx.y << 7;

    // Prefetch 3 K-chunks (A+B per chunk), one commit group per chunk.
    {
        const char* Ab = reinterpret_cast<const char*>(A3);
        const char* Bb = reinterpret_cast<const char*>(B3);
#pragma unroll
        for (int c = 0; c < 3; c++) {
            uint32_t sA = smem_u32(smemb) + c*2*CTILE;
            uint32_t sB = sA + CTILE;
#pragma unroll
            for (int j = 0; j < 4; j++) {
                int idx = tid + j*512;              // 2048 16B-chunks per tile
                int r = idx >> 4, ch = idx & 15;
                long gofA = ((long)(m0 + r)*48 + c*16 + ch) * 16;
                CPASYNC16(sA + r*272 + ch*16, Ab + gofA);
                int gr = n0 + r; gr = (gr < N) ? gr : (N - 1);
                long gofB = ((long)gr*48 + c*16 + ch) * 16;
                CPASYNC16(sB + r*272 + ch*16, Bb + gofB);
            }
            CPCOMMIT();
        }
    }

    const int lane = tid & 31, wid = tid >> 5;
    const int wm = wid >> 2, wn = wid & 3;          // warp tile: rows wm*32, cols wn*32

    uint32_t a_off[2], b_off[2];
#pragma unroll
    for (int mi = 0; mi < 2; mi++) {
        int arow = wm*32 + mi*16 + (lane & 15);
        int acol = (lane >> 4) * 8;
        a_off[mi] = arow*272 + acol*2;
    }
#pragma unroll
    for (int njp = 0; njp < 2; njp++) {
        int brow = wn*32 + njp*16 + ((lane >> 4) & 1)*8 + (lane & 7);
        int bcol = ((lane >> 3) & 1) * 8;
        b_off[njp] = brow*272 + bcol*2;
    }

    float acc[2][4][4];
#pragma unroll
    for (int i = 0; i < 2; i++)
#pragma unroll
        for (int j = 0; j < 4; j++)
#pragma unroll
            for (int q = 0; q < 4; q++) acc[i][j][q] = 0.f;

#pragma unroll
    for (int c = 0; c < 3; c++) {
        if (c == 0)      { CPWAIT(2); }
        else if (c == 1) { CPWAIT(1); }
        else             { CPWAIT(0); }
        __syncthreads();
        uint32_t baseA = smem_u32(smemb) + c*2*CTILE;
        uint32_t baseB = baseA + CTILE;
#pragma unroll
        for (int k = 0; k < 8; k++) {
            uint32_t a[2][4], b[2][4];
#pragma unroll
            for (int mi = 0; mi < 2; mi++)
                LDSM4(a[mi][0], a[mi][1], a[mi][2], a[mi][3], baseA + a_off[mi] + k*32);
#pragma unroll
            for (int njp = 0; njp < 2; njp++)
                LDSM4(b[njp][0], b[njp][1], b[njp][2], b[njp][3], baseB + b_off[njp] + k*32);
#pragma unroll
            for (int mi = 0; mi < 2; mi++)
#pragma unroll
                for (int nj = 0; nj < 4; nj++)
                    MMA16816(acc[mi][nj], a[mi],
                             b[nj >> 1][(nj & 1)*2], b[nj >> 1][(nj & 1)*2 + 1]);
        }
    }

    // Epilogue: acc -> smem Ds[128][132] (reuses dead tiles) -> coalesced stores.
    __syncthreads();                                 // all MMA reads done
    float* Ds = reinterpret_cast<float*>(smemb);
#pragma unroll
    for (int mi = 0; mi < 2; mi++) {
        int r0 = wm*32 + mi*16 + (lane >> 2);        // local rows r0, r0+8
#pragma unroll
        for (int nj = 0; nj < 4; nj++) {
            int c0 = wn*32 + nj*8 + (lane & 3)*2;
            *reinterpret_cast<float2*>(&Ds[r0*132 + c0])     = make_float2(acc[mi][nj][0], acc[mi][nj][1]);
            *reinterpret_cast<float2*>(&Ds[(r0+8)*132 + c0]) = make_float2(acc[mi][nj][2], acc[mi][nj][3]);
        }
    }
    __syncthreads();

    {
        int col = tid & 127, rg = tid >> 7;          // 4 groups x 32 rows
        int gc = n0 + col;
        if (gc < N) {
#pragma unroll 8
            for (int r = rg*32; r < rg*32 + 32; r++)
                C[(long)(m0 + r)*N + gc] = Ds[r*132 + col];
        }
    }
}

// =================================================================================
// split3 for embedding, vectorized: fp32 [n x 128] -> bf16 [n x 384] = [hi|hi|lo]
// =================================================================================
__global__ void split3v_k(const float* __restrict__ src, __nv_bfloat16* __restrict__ dst,
                          int nrows) {
    int i = blockIdx.x * 256 + threadIdx.x;          // nrows*64 pairs
    if (i < nrows * 64) {
        int row = i >> 6, c = (i & 63) * 2;
        float2 v = *reinterpret_cast<const float2*>(src + row*128 + c);
        __nv_bfloat162 hp = __floats2bfloat162_rn(v.x, v.y);
        float lx = v.x - __bfloat162float(hp.x);
        float ly = v.y - __bfloat162float(hp.y);
        __nv_bfloat162 lp = __floats2bfloat162_rn(lx, ly);
        __nv_bfloat16* d = dst + (long)row*384 + c;
        *reinterpret_cast<__nv_bfloat162*>(d)       = hp;
        *reinterpret_cast<__nv_bfloat162*>(d + 128) = hp;
        *reinterpret_cast<__nv_bfloat162*>(d + 256) = lp;
    }
}

// =================================================================================
// prep: transpose weights into g_wt
// =================================================================================
__global__ void prep_t_k(const float* __restrict__ W_ih, const float* __restrict__ W_hh,
                         const float* __restrict__ W1,  const float* __restrict__ W2,
                         const float* __restrict__ Wt,  float* __restrict__ wt) {
    int i = blockIdx.x * 256 + threadIdx.x;
    if (i < OW_HH) {
        int k = i / 384, j = i % 384;
        wt[i] = W_ih[j*128 + k];
    } else if (i < OW_1) {
        int t = i - OW_HH; int k = t / 384, j = t % 384;
        wt[i] = W_hh[j*128 + k];
    } else if (i < OW_2) {
        int t = i - OW_1; int k = t / 128, j = t % 128;
        wt[i] = W1[j*128 + k];
    } else if (i < OW_T) {
        int t = i - OW_2; int k = t / 128, j = t % 128;
        wt[i] = W2[j*128 + k];
    } else if (i < WT_TOTAL) {
        int t = i - OW_T; int k = t / 128, j = t % 128;
        wt[i] = Wt[j*256 + k];
    }
}

// =================================================================================
// Megakernel: one block per session (UNCHANGED from R13).
// =================================================================================
__device__ __forceinline__ float bsum128(float v, float* s4) {
#pragma unroll
    for (int o = 16; o > 0; o >>= 1) v += __shfl_xor_sync(0xffffffffu, v, o);
    int w = threadIdx.x >> 5;
    if ((threadIdx.x & 31) == 0) s4[w] = v;
    __syncthreads();
    v = s4[0] + s4[1] + s4[2] + s4[3];
    __syncthreads();
    return v;
}

__global__ void __launch_bounds__(128) mega_k(
    const int* __restrict__ items, const int* __restrict__ edge,
    const int* __restrict__ seq, const int* __restrict__ mask,
    const float* __restrict__ emb, const float* __restrict__ G,
    const float* __restrict__ wt,
    const float* __restrict__ b_ih, const float* __restrict__ b_hh,
    const float* __restrict__ b1, const float* __restrict__ b2,
    const float* __restrict__ w3, const float* __restrict__ bt,
    const float* __restrict__ gamma, const float* __restrict__ beta,
    __nv_bfloat16* __restrict__ a3)
{
    __shared__ float xs[NS_][H_];
    __shared__ float aggs[NS_][H_];
    __shared__ float hid[L_][H_];
    __shared__ int items_s[NS_];
    __shared__ float a_sh[H_];
    __shared__ float red[4];

    const int b = blockIdx.x, j = threadIdx.x;
    if (j < NS_) items_s[j] = items[b*NS_ + j];
    __syncthreads();

#pragma unroll
    for (int i = 0; i < NS_; i++) xs[i][j] = emb[items_s[i]*H_ + j];
    __syncthreads();

    {
        float mcol[NS_];
#pragma unroll
        for (int i = 0; i < NS_; i++) mcol[i] = 0.f;
#pragma unroll 4
        for (int k = 0; k < H_; k++) {
            float gk = G[k*H_ + j];
#pragma unroll
            for (int i = 0; i < NS_; i++) mcol[i] += xs[i][k] * gk;
        }
#pragma unroll
        for (int i = 0; i < NS_; i++) hid[i][j] = mcol[i];
    }

#pragma unroll
    for (int i = 0; i < NS_; i++) aggs[i][j] = 0.f;
    {
        const int* src = edge + b*EPS_;
        const int* dst = edge + B_*EPS_ + b*EPS_;
#pragma unroll
        for (int e = 0; e < EPS_; e++) {
            int s = src[e] - b*NS_;
            int d = dst[e] - b*NS_;
            aggs[d][j] += hid[s][j];
        }
    }
    __syncthreads();

    {
        const float* wih = wt + OW_IH;
        const float* whh = wt + OW_HH;
        float bi0 = b_ih[j], bi1 = b_ih[H_ + j], bi2 = b_ih[2*H_ + j];
        float bh0 = b_hh[j], bh1 = b_hh[H_ + j], bh2 = b_hh[2*H_ + j];
#pragma unroll
        for (int half = 0; half < 2; half++) {
            float gi0[8], gi1[8], gi2[8], gh0[8], gh1[8], gh2[8];
#pragma unroll
            for (int i = 0; i < 8; i++) {
                gi0[i] = bi0; gi1[i] = bi1; gi2[i] = bi2;
                gh0[i] = bh0; gh1[i] = bh1; gh2[i] = bh2;
            }
#pragma unroll 2
            for (int k = 0; k < H_; k++) {
                float wi0 = wih[k*384 + j], wi1 = wih[k*384 + H_ + j], wi2 = wih[k*384 + 2*H_ + j];
                float wh0 = whh[k*384 + j], wh1 = whh[k*384 + H_ + j], wh2 = whh[k*384 + 2*H_ + j];
#pragma unroll
                for (int i = 0; i < 8; i++) {
                    float ak = aggs[half*8 + i][k];
                    float xk = xs[half*8 + i][k];
                    gi0[i] += ak*wi0; gi1[i] += ak*wi1; gi2[i] += ak*wi2;
                    gh0[i] += xk*wh0; gh1[i] += xk*wh1; gh2[i] += xk*wh2;
                }
            }
            __syncthreads();   // finish READING xs rows before writing them
#pragma unroll
            for (int i = 0; i < 8; i++) {
                float r = 1.f / (1.f + expf(-(gi0[i] + gh0[i])));
                float z = 1.f / (1.f + expf(-(gi1[i] + gh1[i])));
                float n = tanhf(gi2[i] + r*gh2[i]);
                xs[half*8 + i][j] = (1.f - z)*n + z*xs[half*8 + i][j];
            }
        }
    }

#pragma unroll
    for (int l = 0; l < L_; l++) {
        int s = seq[b*L_ + l];
        float v = 0.f;
        if (s != 0) {
            int idx = -1;
#pragma unroll
            for (int q = 0; q < NS_; q++) if (idx < 0 && items_s[q] == s) idx = q;
            v = (idx >= 0) ? xs[idx][j] : emb[s*H_ + j];
        }
        hid[l][j] = v;
    }
    int len = 0;
#pragma unroll
    for (int l = 0; l < L_; l++) len += mask[b*L_ + l];
    __syncthreads();

    {
        const float* w1t = wt + OW_1;
        const float* w2t = wt + OW_2;
        const float* wtt = wt + OW_T;
        const float* ht = hid[len - 1];
        float q1 = b1[j];
#pragma unroll 8
        for (int k = 0; k < H_; k++) q1 += ht[k] * w1t[k*H_ + j];
        float w3j = w3[j];
        float bb2 = b2[j];

        float acc = 0.f;
        for (int l = 0; l < L_; l++) {
            float q2 = bb2;
#pragma unroll 8
            for (int k = 0; k < H_; k++) q2 += hid[l][k] * w2t[k*H_ + j];
            float v = (1.f / (1.f + expf(-(q1 + q2)))) * w3j;
            float alpha = bsum128(v, red);
            acc += alpha * hid[l][j] * (float)mask[b*L_ + l];
        }
        a_sh[j] = acc;
        __syncthreads();

        float o = bt[j];
#pragma unroll 8
        for (int k = 0; k < H_; k++) o += a_sh[k] * wtt[k*H_ + j];
#pragma unroll 8
        for (int k = 0; k < H_; k++) o += ht[k] * wtt[(H_ + k)*H_ + j];

        float mu = bsum128(o, red) * (1.f / H_);
        float d = o - mu;
        float var = bsum128(d*d, red) * (1.f / H_);
        float aout = d * rsqrtf(var + 1e-5f) * gamma[j] + beta[j];

        __nv_bfloat16 h = __float2bfloat16(aout);
        __nv_bfloat16 lo = __float2bfloat16(aout - __bfloat162float(h));
        a3[b*384 + j]        = h;
        a3[b*384 + H_ + j]   = lo;
        a3[b*384 + 2*H_ + j] = h;
    }
}

// =================================================================================
extern "C" void kernel_launch(void* const* d_in, const int* in_sizes, int n_in,
                              void* d_out, int out_size)
{
    const int*   items    = (const int*)d_in[0];
    const int*   edge     = (const int*)d_in[1];
    const int*   sequence = (const int*)d_in[2];
    const int*   mask     = (const int*)d_in[3];
    const float* emb      = (const float*)d_in[4];
    const float* ggnn_w   = (const float*)d_in[5];
    const float* W_ih     = (const float*)d_in[6];
    const float* W_hh     = (const float*)d_in[7];
    const float* b_ih     = (const float*)d_in[8];
    const float* b_hh     = (const float*)d_in[9];
    const float* W1       = (const float*)d_in[10];
    const float* b1       = (const float*)d_in[11];
    const float* W2       = (const float*)d_in[12];
    const float* b2       = (const float*)d_in[13];
    const float* w3       = (const float*)d_in[14];
    const float* Wt       = (const float*)d_in[15];
    const float* bt       = (const float*)d_in[16];
    const float* gamma    = (const float*)d_in[17];
    const float* beta     = (const float*)d_in[18];
    float* out = (float*)d_out;

    __nv_bfloat16 *pe3, *pa3;
    float* pwt;
    cudaGetSymbolAddress((void**)&pe3, g_e3);
    cudaGetSymbolAddress((void**)&pa3, g_a3);
    cudaGetSymbolAddress((void**)&pwt, g_wt);

    cudaFuncSetAttribute(scores_mma_k, cudaFuncAttributeMaxDynamicSharedMemorySize, TCS_SMEM);

    // 1) split embedding[1:] into K=384 [hi|hi|lo]
    split3v_k<<<((V_-1)*64 + 255)/256, 256>>>(emb + H_, pe3, V_ - 1);
    // 2) transpose weights
    prep_t_k<<<(WT_TOTAL + 255)/256, 256>>>(W_ih, W_hh, W1, W2, Wt, pwt);
    // 3) fused per-session pipeline -> a3[512,384]
    mega_k<<<B_, 128>>>(items, edge, sequence, mask, emb, ggnn_w, pwt,
                        b_ih, b_hh, b1, b2, w3, bt, gamma, beta, pa3);
    // 4) tensor-core scores (512 threads, smem-staged epilogue)
    scores_mma_k<<<dim3(B_/128, (V_ - 1 + 127)/128), 512, TCS_SMEM>>>(pa3, pe3, out, V_ - 1);
}

// round 15
// speedup vs baseline: 3.6310x; 1.0192x over previous
#include <cuda_runtime.h>
#include <cuda_bf16.h>
#include <cstdint>
#include <math.h>

#define B_   512
#define L_   20
#define NS_  16
#define EPS_ 32
#define H_   128
#define V_   100000

// ---------------- device scratch (no runtime allocation allowed) ----------------
// 2-segment bf16 splits, K=256 rows = [hi(128) | lo(128)].
// Scores = A_hi*B_hi + A_lo*B_hi + A_hi*B_lo (lo*lo ~ 2^-18 dropped)
__device__ __nv_bfloat16 g_e2[(V_-1)*256];
__device__ __nv_bfloat16 g_a2[B_*256];
// transposed weights: WihT[128][384] WhhT[128][384] W1T[128][128] W2T[128][128] WtT[256][128]
#define OW_IH 0
#define OW_HH 49152
#define OW_1  98304
#define OW_2  114688
#define OW_T  131072
#define WT_TOTAL 163840
__device__ float g_wt[WT_TOTAL];

// =================================================================================
// mma.sync bf16 scores GEMM: C[M,N] = A2[M,256-split] * B2[N,256-split]^T (fp32 acc)
// CTA tile 128m x 256n, 512 thr / 16 warps (2m x 8n), warp tile 64x32, m16n8k16.
// 4 resident smem tiles (A_hi, A_lo, B_hi(256r), B_lo(256r)) = 209 KB; 3 passes
// reuse them: hh, lh, hl. cp.async groups overlap B_lo load with passes 0-1.
// =================================================================================
#define CROW   136
#define CTILE  (128*CROW*2)             // 34816 B (128 rows)
#define TCS_SMEM (6*CTILE)              // A_hi, A_lo, B_hi(2), B_lo(2)

__device__ __forceinline__ uint32_t smem_u32(const void* p) {
    uint32_t a;
    asm("{ .reg .u64 t; cvta.to.shared.u64 t, %1; cvt.u32.u64 %0, t; }" : "=r"(a) : "l"(p));
    return a;
}
#define CPASYNC16(dst, src) \
    asm volatile("cp.async.cg.shared.global [%0], [%1], 16;" :: "r"(dst), "l"(src))
#define CPCOMMIT() asm volatile("cp.async.commit_group;" ::: "memory")
#define CPWAIT(n)  asm volatile("cp.async.wait_group " #n ";" ::: "memory")
#define LDSM4(r0,r1,r2,r3,addr) \
    asm volatile("ldmatrix.sync.aligned.m8n8.x4.shared.b16 {%0,%1,%2,%3}, [%4];" \
        : "=r"(r0), "=r"(r1), "=r"(r2), "=r"(r3) : "r"(addr))
#define MMA16816(c, a, b0, b1) \
    asm volatile("mma.sync.aligned.m16n8k16.row.col.f32.bf16.bf16.f32 " \
        "{%0,%1,%2,%3}, {%4,%5,%6,%7}, {%8,%9}, {%0,%1,%2,%3};" \
        : "+f"((c)[0]), "+f"((c)[1]), "+f"((c)[2]), "+f"((c)[3]) \
        : "r"((a)[0]), "r"((a)[1]), "r"((a)[2]), "r"((a)[3]), "r"(b0), "r"(b1))

__global__ void __launch_bounds__(512, 1) scores_mma_k(
    const __nv_bfloat16* __restrict__ A2, const __nv_bfloat16* __restrict__ B2,
    float* __restrict__ C, int N)
{
    extern __shared__ __align__(16) __nv_bfloat16 smemb[];
    const int tid = threadIdx.x;
    const int m0 = blockIdx.x << 7;          // 4 m-blocks (fast dim -> B reuse via L2)
    const int n0 = blockIdx.y << 8;          // 256-wide n-blocks
    const uint32_t sbase = smem_u32(smemb);

    // ---- async loads: g0=A_hi, g1=B_hi, g2=A_lo, g3=B_lo ----
    {
        const char* Ab = reinterpret_cast<const char*>(A2);
        const char* Bb = reinterpret_cast<const char*>(B2);
        // A_hi (2048 chunks)
#pragma unroll
        for (int j = 0; j < 4; j++) {
            int idx = tid + j*512; int r = idx >> 4, ch = idx & 15;
            CPASYNC16(sbase + r*272 + ch*16, Ab + (long)(m0 + r)*512 + ch*16);
        }
        CPCOMMIT();
        // B_hi (4096 chunks, 256 rows)
#pragma unroll
        for (int j = 0; j < 8; j++) {
            int idx = tid + j*512; int r = idx >> 4, ch = idx & 15;
            int gr = n0 + r; gr = (gr < N) ? gr : (N - 1);
            CPASYNC16(sbase + 2*CTILE + r*272 + ch*16, Bb + (long)gr*512 + ch*16);
        }
        CPCOMMIT();
        // A_lo
#pragma unroll
        for (int j = 0; j < 4; j++) {
            int idx = tid + j*512; int r = idx >> 4, ch = idx & 15;
            CPASYNC16(sbase + CTILE + r*272 + ch*16, Ab + (long)(m0 + r)*512 + 256 + ch*16);
        }
        CPCOMMIT();
        // B_lo
#pragma unroll
        for (int j = 0; j < 8; j++) {
            int idx = tid + j*512; int r = idx >> 4, ch = idx & 15;
            int gr = n0 + r; gr = (gr < N) ? gr : (N - 1);
            CPASYNC16(sbase + 4*CTILE + r*272 + ch*16, Bb + (long)gr*512 + 256 + ch*16);
        }
        CPCOMMIT();
    }

    const int lane = tid & 31, wid = tid >> 5;
    const int wm = wid >> 3, wn = wid & 7;   // warp tile: rows wm*64, cols wn*32

    uint32_t a_off[4], b_off[2];
#pragma unroll
    for (int mi = 0; mi < 4; mi++) {
        int arow = wm*64 + mi*16 + (lane & 15);
        int acol = (lane >> 4) * 8;
        a_off[mi] = arow*272 + acol*2;
    }
#pragma unroll
    for (int njp = 0; njp < 2; njp++) {
        int brow = wn*32 + njp*16 + ((lane >> 4) & 1)*8 + (lane & 7);
        int bcol = ((lane >> 3) & 1) * 8;
        b_off[njp] = brow*272 + bcol*2;
    }

    float acc[4][4][4];
#pragma unroll
    for (int i = 0; i < 4; i++)
#pragma unroll
        for (int j = 0; j < 4; j++)
#pragma unroll
            for (int q = 0; q < 4; q++) acc[i][j][q] = 0.f;

    // ---- 3 passes over resident tiles: hh, lh, hl ----
#pragma unroll
    for (int p = 0; p < 3; p++) {
        if (p == 0)      { CPWAIT(2); }      // A_hi + B_hi ready
        else if (p == 1) { CPWAIT(1); }      // + A_lo
        else             { CPWAIT(0); }      // + B_lo
        __syncthreads();
        uint32_t baseA = sbase + ((p == 1) ? CTILE : 0);
        uint32_t baseB = sbase + 2*CTILE + ((p == 2) ? 2*CTILE : 0);
#pragma unroll
        for (int k = 0; k < 8; k++) {
            uint32_t a[4][4];
#pragma unroll
            for (int mi = 0; mi < 4; mi++)
                LDSM4(a[mi][0], a[mi][1], a[mi][2], a[mi][3], baseA + a_off[mi] + k*32);
#pragma unroll
            for (int njp = 0; njp < 2; njp++) {
                uint32_t b[4];
                LDSM4(b[0], b[1], b[2], b[3], baseB + b_off[njp] + k*32);
#pragma unroll
                for (int mi = 0; mi < 4; mi++) {
                    MMA16816(acc[mi][njp*2],     a[mi], b[0], b[1]);
                    MMA16816(acc[mi][njp*2 + 1], a[mi], b[2], b[3]);
                }
            }
        }
    }

    // ---- epilogue: acc -> smem Ds[128][260] -> coalesced stores ----
    __syncthreads();
    float* Ds = reinterpret_cast<float*>(smemb);
#pragma unroll
    for (int mi = 0; mi < 4; mi++) {
        int r0 = wm*64 + mi*16 + (lane >> 2);
#pragma unroll
        for (int nj = 0; nj < 4; nj++) {
            int c0 = wn*32 + nj*8 + (lane & 3)*2;
            *reinterpret_cast<float2*>(&Ds[r0*260 + c0])     = make_float2(acc[mi][nj][0], acc[mi][nj][1]);
            *reinterpret_cast<float2*>(&Ds[(r0+8)*260 + c0]) = make_float2(acc[mi][nj][2], acc[mi][nj][3]);
        }
    }
    __syncthreads();
    {
        int col = tid & 255, rg = tid >> 8;      // 2 groups x 64 rows
        int gc = n0 + col;
        if (gc < N) {
#pragma unroll 8
            for (int r = rg*64; r < rg*64 + 64; r++)
                C[(long)(m0 + r)*N + gc] = Ds[r*260 + col];
        }
    }
}

// =================================================================================
// split2 for embedding, vectorized: fp32 [n x 128] -> bf16 [n x 256] = [hi|lo]
// =================================================================================
__global__ void split2v_k(const float* __restrict__ src, __nv_bfloat16* __restrict__ dst,
                          int nrows) {
    int i = blockIdx.x * 256 + threadIdx.x;          // nrows*64 pairs
    if (i < nrows * 64) {
        int row = i >> 6, c = (i & 63) * 2;
        float2 v = *reinterpret_cast<const float2*>(src + row*128 + c);
        __nv_bfloat162 hp = __floats2bfloat162_rn(v.x, v.y);
        float lx = v.x - __bfloat162float(hp.x);
        float ly = v.y - __bfloat162float(hp.y);
        __nv_bfloat162 lp = __floats2bfloat162_rn(lx, ly);
        __nv_bfloat16* d = dst + (long)row*256 + c;
        *reinterpret_cast<__nv_bfloat162*>(d)       = hp;
        *reinterpret_cast<__nv_bfloat162*>(d + 128) = lp;
    }
}

// =================================================================================
// prep: transpose weights into g_wt
// =================================================================================
__global__ void prep_t_k(const float* __restrict__ W_ih, const float* __restrict__ W_hh,
                         const float* __restrict__ W1,  const float* __restrict__ W2,
                         const float* __restrict__ Wt,  float* __restrict__ wt) {
    int i = blockIdx.x * 256 + threadIdx.x;
    if (i < OW_HH) {
        int k = i / 384, j = i % 384;
        wt[i] = W_ih[j*128 + k];
    } else if (i < OW_1) {
        int t = i - OW_HH; int k = t / 384, j = t % 384;
        wt[i] = W_hh[j*128 + k];
    } else if (i < OW_2) {
        int t = i - OW_1; int k = t / 128, j = t % 128;
        wt[i] = W1[j*128 + k];
    } else if (i < OW_T) {
        int t = i - OW_2; int k = t / 128, j = t % 128;
        wt[i] = W2[j*128 + k];
    } else if (i < WT_TOTAL) {
        int t = i - OW_T; int k = t / 128, j = t % 128;
        wt[i] = Wt[j*256 + k];
    }
}

// =================================================================================
// Megakernel: one block per session. Attention now uses a single reduction phase
// (all 20 v-vectors to smem, one barrier, per-warp shuffle reductions).
// =================================================================================
__device__ __forceinline__ float bsum128(float v, float* s4) {
#pragma unroll
    for (int o = 16; o > 0; o >>= 1) v += __shfl_xor_sync(0xffffffffu, v, o);
    int w = threadIdx.x >> 5;
    if ((threadIdx.x & 31) == 0) s4[w] = v;
    __syncthreads();
    v = s4[0] + s4[1] + s4[2] + s4[3];
    __syncthreads();
    return v;
}

__global__ void __launch_bounds__(128) mega_k(
    const int* __restrict__ items, const int* __restrict__ edge,
    const int* __restrict__ seq, const int* __restrict__ mask,
    const float* __restrict__ emb, const float* __restrict__ G,
    const float* __restrict__ wt,
    const float* __restrict__ b_ih, const float* __restrict__ b_hh,
    const float* __restrict__ b1, const float* __restrict__ b2,
    const float* __restrict__ w3, const float* __restrict__ bt,
    const float* __restrict__ gamma, const float* __restrict__ beta,
    __nv_bfloat16* __restrict__ a2)
{
    __shared__ float xs[NS_][H_];
    __shared__ float aggs[NS_][H_];
    __shared__ float hid[L_][H_];
    __shared__ float vs[L_][H_];
    __shared__ float alpha_sh[L_];
    __shared__ int items_s[NS_];
    __shared__ float a_sh[H_];
    __shared__ float red[4];

    const int b = blockIdx.x, j = threadIdx.x;
    const int lane = j & 31, wid = j >> 5;
    if (j < NS_) items_s[j] = items[b*NS_ + j];
    __syncthreads();

#pragma unroll
    for (int i = 0; i < NS_; i++) xs[i][j] = emb[items_s[i]*H_ + j];
    __syncthreads();

    // m = x @ G  (into hid rows 0..15)
    {
        float mcol[NS_];
#pragma unroll
        for (int i = 0; i < NS_; i++) mcol[i] = 0.f;
#pragma unroll 4
        for (int k = 0; k < H_; k++) {
            float gk = G[k*H_ + j];
#pragma unroll
            for (int i = 0; i < NS_; i++) mcol[i] += xs[i][k] * gk;
        }
#pragma unroll
        for (int i = 0; i < NS_; i++) hid[i][j] = mcol[i];
    }

    // agg = segment_sum  (column-local)
#pragma unroll
    for (int i = 0; i < NS_; i++) aggs[i][j] = 0.f;
    {
        const int* src = edge + b*EPS_;
        const int* dst = edge + B_*EPS_ + b*EPS_;
#pragma unroll
        for (int e = 0; e < EPS_; e++) {
            int s = src[e] - b*NS_;
            int d = dst[e] - b*NS_;
            aggs[d][j] += hid[s][j];
        }
    }
    __syncthreads();

    // GRU (two halves of 8 rows)
    {
        const float* wih = wt + OW_IH;
        const float* whh = wt + OW_HH;
        float bi0 = b_ih[j], bi1 = b_ih[H_ + j], bi2 = b_ih[2*H_ + j];
        float bh0 = b_hh[j], bh1 = b_hh[H_ + j], bh2 = b_hh[2*H_ + j];
#pragma unroll
        for (int half = 0; half < 2; half++) {
            float gi0[8], gi1[8], gi2[8], gh0[8], gh1[8], gh2[8];
#pragma unroll
            for (int i = 0; i < 8; i++) {
                gi0[i] = bi0; gi1[i] = bi1; gi2[i] = bi2;
                gh0[i] = bh0; gh1[i] = bh1; gh2[i] = bh2;
            }
#pragma unroll 2
            for (int k = 0; k < H_; k++) {
                float wi0 = wih[k*384 + j], wi1 = wih[k*384 + H_ + j], wi2 = wih[k*384 + 2*H_ + j];
                float wh0 = whh[k*384 + j], wh1 = whh[k*384 + H_ + j], wh2 = whh[k*384 + 2*H_ + j];
#pragma unroll
                for (int i = 0; i < 8; i++) {
                    float ak = aggs[half*8 + i][k];
                    float xk = xs[half*8 + i][k];
                    gi0[i] += ak*wi0; gi1[i] += ak*wi1; gi2[i] += ak*wi2;
                    gh0[i] += xk*wh0; gh1[i] += xk*wh1; gh2[i] += xk*wh2;
                }
            }
            __syncthreads();   // finish READING xs rows before writing them
#pragma unroll
            for (int i = 0; i < 8; i++) {
                float r = 1.f / (1.f + expf(-(gi0[i] + gh0[i])));
                float z = 1.f / (1.f + expf(-(gi1[i] + gh1[i])));
                float n = tanhf(gi2[i] + r*gh2[i]);
                xs[half*8 + i][j] = (1.f - z)*n + z*xs[half*8 + i][j];
            }
        }
    }

    // hidden (column-local)
#pragma unroll
    for (int l = 0; l < L_; l++) {
        int s = seq[b*L_ + l];
        float v = 0.f;
        if (s != 0) {
            int idx = -1;
#pragma unroll
            for (int q = 0; q < NS_; q++) if (idx < 0 && items_s[q] == s) idx = q;
            v = (idx >= 0) ? xs[idx][j] : emb[s*H_ + j];
        }
        hid[l][j] = v;
    }
    int len = 0;
#pragma unroll
    for (int l = 0; l < L_; l++) len += mask[b*L_ + l];
    __syncthreads();

    // attention (single reduction phase) + hybrid + layernorm + split2 epilogue
    {
        const float* w1t = wt + OW_1;
        const float* w2t = wt + OW_2;
        const float* wtt = wt + OW_T;
        const float* ht = hid[len - 1];
        float q1 = b1[j];
#pragma unroll 8
        for (int k = 0; k < H_; k++) q1 += ht[k] * w1t[k*H_ + j];
        float w3j = w3[j];
        float bb2 = b2[j];

        for (int l = 0; l < L_; l++) {
            float q2 = bb2;
#pragma unroll 8
            for (int k = 0; k < H_; k++) q2 += hid[l][k] * w2t[k*H_ + j];
            vs[l][j] = (1.f / (1.f + expf(-(q1 + q2)))) * w3j;
        }
        __syncthreads();

        // per-warp reduction: warp w handles rows l = w, w+4, ...
        for (int l = wid; l < L_; l += 4) {
            float s = vs[l][lane] + vs[l][lane + 32] + vs[l][lane + 64] + vs[l][lane + 96];
#pragma unroll
            for (int o = 16; o > 0; o >>= 1) s += __shfl_xor_sync(0xffffffffu, s, o);
            if (lane == 0) alpha_sh[l] = s;
        }
        __syncthreads();

        float acc = 0.f;
#pragma unroll
        for (int l = 0; l < L_; l++)
            acc += alpha_sh[l] * hid[l][j] * (float)mask[b*L_ + l];
        a_sh[j] = acc;
        __syncthreads();

        float o = bt[j];
#pragma unroll 8
        for (int k = 0; k < H_; k++) o += a_sh[k] * wtt[k*H_ + j];
#pragma unroll 8
        for (int k = 0; k < H_; k++) o += ht[k] * wtt[(H_ + k)*H_ + j];

        float mu = bsum128(o, red) * (1.f / H_);
        float d = o - mu;
        float var = bsum128(d*d, red) * (1.f / H_);
        float aout = d * rsqrtf(var + 1e-5f) * gamma[j] + beta[j];

        __nv_bfloat16 h = __float2bfloat16(aout);
        __nv_bfloat16 lo = __float2bfloat16(aout - __bfloat162float(h));
        a2[b*256 + j]       = h;
        a2[b*256 + H_ + j]  = lo;
    }
}

// =================================================================================
extern "C" void kernel_launch(void* const* d_in, const int* in_sizes, int n_in,
                              void* d_out, int out_size)
{
    const int*   items    = (const int*)d_in[0];
    const int*   edge     = (const int*)d_in[1];
    const int*   sequence = (const int*)d_in[2];
    const int*   mask     = (const int*)d_in[3];
    const float* emb      = (const float*)d_in[4];
    const float* ggnn_w   = (const float*)d_in[5];
    const float* W_ih     = (const float*)d_in[6];
    const float* W_hh     = (const float*)d_in[7];
    const float* b_ih     = (const float*)d_in[8];
    const float* b_hh     = (const float*)d_in[9];
    const float* W1       = (const float*)d_in[10];
    const float* b1       = (const float*)d_in[11];
    const float* W2       = (const float*)d_in[12];
    const float* b2       = (const float*)d_in[13];
    const float* w3       = (const float*)d_in[14];
    const float* Wt       = (const float*)d_in[15];
    const float* bt       = (const float*)d_in[16];
    const float* gamma    = (const float*)d_in[17];
    const float* beta     = (const float*)d_in[18];
    float* out = (float*)d_out;

    __nv_bfloat16 *pe2, *pa2;
    float* pwt;
    cudaGetSymbolAddress((void**)&pe2, g_e2);
    cudaGetSymbolAddress((void**)&pa2, g_a2);
    cudaGetSymbolAddress((void**)&pwt, g_wt);

    cudaFuncSetAttribute(scores_mma_k, cudaFuncAttributeMaxDynamicSharedMemorySize, TCS_SMEM);

    // 1) split embedding[1:] into K=256 [hi|lo]
    split2v_k<<<((V_-1)*64 + 255)/256, 256>>>(emb + H_, pe2, V_ - 1);
    // 2) transpose weights
    prep_t_k<<<(WT_TOTAL + 255)/256, 256>>>(W_ih, W_hh, W1, W2, Wt, pwt);
    // 3) fused per-session pipeline -> a2[512,256]
    mega_k<<<B_, 128>>>(items, edge, sequence, mask, emb, ggnn_w, pwt,
                        b_ih, b_hh, b1, b2, w3, bt, gamma, beta, pa2);
    // 4) tensor-core scores, 128x256 tiles
    scores_mma_k<<<dim3(B_/128, (V_ - 1 + 255)/256), 512, TCS_SMEM>>>(pa2, pe2, out, V_ - 1);
}

// round 16
// speedup vs baseline: 3.9493x; 1.0877x over previous
#include <cuda_runtime.h>
#include <cuda_bf16.h>
#include <cstdint>
#include <math.h>

#define B_   512
#define L_   20
#define NS_  16
#define EPS_ 32
#define H_   128
#define V_   100000

// ---------------- device scratch (no runtime allocation allowed) ----------------
// 2-segment bf16 splits, row = [hi(128) | lo(128)] contiguous (512 B/row).
// Scores = A_hi*B_hi + A_lo*B_hi + A_hi*B_lo (lo*lo ~ 2^-18 dropped)
__device__ __nv_bfloat16 g_e2[(V_-1)*256];
__device__ __nv_bfloat16 g_a2[B_*256];
// transposed weights: WihT[128][384] WhhT[128][384] W1T[128][128] W2T[128][128] WtT[256][128]
#define OW_IH 0
#define OW_HH 49152
#define OW_1  98304
#define OW_2  114688
#define OW_T  131072
#define WT_TOTAL 163840
__device__ float g_wt[WT_TOTAL];

// =================================================================================
// mma.sync bf16 scores GEMM: C[M,N] = A2 * B2^T with 3 k-offset passes (hh, lh, hl).
// CTA tile 64m x 128n, 256 thr / 8 warps (2m x 4n), warp tile 32x32, m16n8k16.
// Rows stored [hi|lo] contiguous, stride 528 B (33x16B, odd -> ldmatrix conflict-
// free). smem = A 33.8KB + B 67.6KB = 101.4KB -> 2 CTAs/SM (latency overlap).
// =================================================================================
#define AROW   528                       // smem row stride (bytes) for 256 bf16 + pad
#define ATILE  (64*AROW)                 // 33792 B
#define BTILE  (128*AROW)                // 67584 B
#define TCS_SMEM (ATILE + BTILE)         // 101376 B

__device__ __forceinline__ uint32_t smem_u32(const void* p) {
    uint32_t a;
    asm("{ .reg .u64 t; cvta.to.shared.u64 t, %1; cvt.u32.u64 %0, t; }" : "=r"(a) : "l"(p));
    return a;
}
#define CPASYNC16(dst, src) \
    asm volatile("cp.async.cg.shared.global [%0], [%1], 16;" :: "r"(dst), "l"(src))
#define CPCOMMIT() asm volatile("cp.async.commit_group;" ::: "memory")
#define CPWAIT(n)  asm volatile("cp.async.wait_group " #n ";" ::: "memory")
#define LDSM4(r0,r1,r2,r3,addr) \
    asm volatile("ldmatrix.sync.aligned.m8n8.x4.shared.b16 {%0,%1,%2,%3}, [%4];" \
        : "=r"(r0), "=r"(r1), "=r"(r2), "=r"(r3) : "r"(addr))
#define MMA16816(c, a, b0, b1) \
    asm volatile("mma.sync.aligned.m16n8k16.row.col.f32.bf16.bf16.f32 " \
        "{%0,%1,%2,%3}, {%4,%5,%6,%7}, {%8,%9}, {%0,%1,%2,%3};" \
        : "+f"((c)[0]), "+f"((c)[1]), "+f"((c)[2]), "+f"((c)[3]) \
        : "r"((a)[0]), "r"((a)[1]), "r"((a)[2]), "r"((a)[3]), "r"(b0), "r"(b1))

__global__ void __launch_bounds__(256, 2) scores_mma_k(
    const __nv_bfloat16* __restrict__ A2, const __nv_bfloat16* __restrict__ B2,
    float* __restrict__ C, int N)
{
    extern __shared__ __align__(16) __nv_bfloat16 smemb[];
    const int tid = threadIdx.x;
    const int m0 = blockIdx.x << 6;          // 8 m-blocks (fast -> B reuse via L2)
    const int n0 = blockIdx.y << 7;          // 128-wide n-blocks
    const uint32_t sbase = smem_u32(smemb);

    // ---- async loads: g0 = hi halves (A then B), g1 = lo halves ----
    {
        const char* Ab = reinterpret_cast<const char*>(A2);
        const char* Bb = reinterpret_cast<const char*>(B2);
#pragma unroll
        for (int h = 0; h < 2; h++) {
            int off = h * 256;               // byte offset of lo half in both src & dst
            // A: 64 rows x 16 chunks = 1024
#pragma unroll
            for (int j = 0; j < 4; j++) {
                int idx = tid + j*256; int r = idx >> 4, ch = idx & 15;
                CPASYNC16(sbase + r*AROW + off + ch*16,
                          Ab + (long)(m0 + r)*512 + off + ch*16);
            }
            // B: 128 rows x 16 chunks = 2048
#pragma unroll
            for (int j = 0; j < 8; j++) {
                int idx = tid + j*256; int r = idx >> 4, ch = idx & 15;
                int gr = n0 + r; gr = (gr < N) ? gr : (N - 1);
                CPASYNC16(sbase + ATILE + r*AROW + off + ch*16,
                          Bb + (long)gr*512 + off + ch*16);
            }
            CPCOMMIT();
        }
    }

    const int lane = tid & 31, wid = tid >> 5;
    const int wm = wid >> 2, wn = wid & 3;   // warp tile: rows wm*32, cols wn*32

    uint32_t a_off[2], b_off[2];
#pragma unroll
    for (int mi = 0; mi < 2; mi++) {
        int arow = wm*32 + mi*16 + (lane & 15);
        int acol = (lane >> 4) * 8;
        a_off[mi] = arow*AROW + acol*2;
    }
#pragma unroll
    for (int njp = 0; njp < 2; njp++) {
        int brow = wn*32 + njp*16 + ((lane >> 4) & 1)*8 + (lane & 7);
        int bcol = ((lane >> 3) & 1) * 8;
        b_off[njp] = brow*AROW + bcol*2;
    }

    float acc[2][4][4];
#pragma unroll
    for (int i = 0; i < 2; i++)
#pragma unroll
        for (int j = 0; j < 4; j++)
#pragma unroll
            for (int q = 0; q < 4; q++) acc[i][j][q] = 0.f;

    // ---- 3 passes via k-offsets: p0 = hh, p1 = lh (A+256), p2 = hl (B+256) ----
#pragma unroll
    for (int p = 0; p < 3; p++) {
        if (p == 0) { CPWAIT(1); __syncthreads(); }
        else if (p == 1) { CPWAIT(0); __syncthreads(); }
        uint32_t baseA = sbase + ((p == 1) ? 256 : 0);
        uint32_t baseB = sbase + ATILE + ((p == 2) ? 256 : 0);
#pragma unroll
        for (int k = 0; k < 8; k++) {
            uint32_t a[2][4];
#pragma unroll
            for (int mi = 0; mi < 2; mi++)
                LDSM4(a[mi][0], a[mi][1], a[mi][2], a[mi][3], baseA + a_off[mi] + k*32);
#pragma unroll
            for (int njp = 0; njp < 2; njp++) {
                uint32_t b[4];
                LDSM4(b[0], b[1], b[2], b[3], baseB + b_off[njp] + k*32);
#pragma unroll
                for (int mi = 0; mi < 2; mi++) {
                    MMA16816(acc[mi][njp*2],     a[mi], b[0], b[1]);
                    MMA16816(acc[mi][njp*2 + 1], a[mi], b[2], b[3]);
                }
            }
        }
    }

    // ---- epilogue: acc -> smem Ds[64][132] (overlays A tile) -> coalesced ----
    __syncthreads();
    float* Ds = reinterpret_cast<float*>(smemb);
#pragma unroll
    for (int mi = 0; mi < 2; mi++) {
        int r0 = wm*32 + mi*16 + (lane >> 2);
#pragma unroll
        for (int nj = 0; nj < 4; nj++) {
            int c0 = wn*32 + nj*8 + (lane & 3)*2;
            *reinterpret_cast<float2*>(&Ds[r0*132 + c0])     = make_float2(acc[mi][nj][0], acc[mi][nj][1]);
            *reinterpret_cast<float2*>(&Ds[(r0+8)*132 + c0]) = make_float2(acc[mi][nj][2], acc[mi][nj][3]);
        }
    }
    __syncthreads();
    {
        int col = tid & 127, rg = tid >> 7;      // 2 groups x 32 rows
        int gc = n0 + col;
        if (gc < N) {
#pragma unroll 8
            for (int r = rg*32; r < rg*32 + 32; r++)
                C[(long)(m0 + r)*N + gc] = Ds[r*132 + col];
        }
    }
}

// =================================================================================
// prep: fused embedding split2 + weight transposes (disjoint block ranges)
// =================================================================================
#define NBS_SPLIT (((V_-1)*64 + 255)/256)
#define NBW_WT    (WT_TOTAL/256)

__global__ void prep_k(const float* __restrict__ emb1, __nv_bfloat16* __restrict__ e2,
                       const float* __restrict__ W_ih, const float* __restrict__ W_hh,
                       const float* __restrict__ W1,  const float* __restrict__ W2,
                       const float* __restrict__ Wt,  float* __restrict__ wt) {
    if (blockIdx.x < NBS_SPLIT) {
        int i = blockIdx.x * 256 + threadIdx.x;      // (V-1)*64 pairs
        if (i < (V_-1) * 64) {
            int row = i >> 6, c = (i & 63) * 2;
            float2 v = *reinterpret_cast<const float2*>(emb1 + row*128 + c);
            __nv_bfloat162 hp = __floats2bfloat162_rn(v.x, v.y);
            float lx = v.x - __bfloat162float(hp.x);
            float ly = v.y - __bfloat162float(hp.y);
            __nv_bfloat162 lp = __floats2bfloat162_rn(lx, ly);
            __nv_bfloat16* d = e2 + (long)row*256 + c;
            *reinterpret_cast<__nv_bfloat162*>(d)       = hp;
            *reinterpret_cast<__nv_bfloat162*>(d + 128) = lp;
        }
    } else {
        int i = (blockIdx.x - NBS_SPLIT) * 256 + threadIdx.x;
        if (i < OW_HH) {
            int k = i / 384, j = i % 384;
            wt[i] = W_ih[j*128 + k];
        } else if (i < OW_1) {
            int t = i - OW_HH; int k = t / 384, j = t % 384;
            wt[i] = W_hh[j*128 + k];
        } else if (i < OW_2) {
            int t = i - OW_1; int k = t / 128, j = t % 128;
            wt[i] = W1[j*128 + k];
        } else if (i < OW_T) {
            int t = i - OW_2; int k = t / 128, j = t % 128;
            wt[i] = W2[j*128 + k];
        } else if (i < WT_TOTAL) {
            int t = i - OW_T; int k = t / 128, j = t % 128;
            wt[i] = Wt[j*256 + k];
        }
    }
}

// =================================================================================
// Megakernel: one block per session (UNCHANGED from R15).
// =================================================================================
__device__ __forceinline__ float bsum128(float v, float* s4) {
#pragma unroll
    for (int o = 16; o > 0; o >>= 1) v += __shfl_xor_sync(0xffffffffu, v, o);
    int w = threadIdx.x >> 5;
    if ((threadIdx.x & 31) == 0) s4[w] = v;
    __syncthreads();
    v = s4[0] + s4[1] + s4[2] + s4[3];
    __syncthreads();
    return v;
}

__global__ void __launch_bounds__(128) mega_k(
    const int* __restrict__ items, const int* __restrict__ edge,
    const int* __restrict__ seq, const int* __restrict__ mask,
    const float* __restrict__ emb, const float* __restrict__ G,
    const float* __restrict__ wt,
    const float* __restrict__ b_ih, const float* __restrict__ b_hh,
    const float* __restrict__ b1, const float* __restrict__ b2,
    const float* __restrict__ w3, const float* __restrict__ bt,
    const float* __restrict__ gamma, const float* __restrict__ beta,
    __nv_bfloat16* __restrict__ a2)
{
    __shared__ float xs[NS_][H_];
    __shared__ float aggs[NS_][H_];
    __shared__ float hid[L_][H_];
    __shared__ float vs[L_][H_];
    __shared__ float alpha_sh[L_];
    __shared__ int items_s[NS_];
    __shared__ float a_sh[H_];
    __shared__ float red[4];

    const int b = blockIdx.x, j = threadIdx.x;
    const int lane = j & 31, wid = j >> 5;
    if (j < NS_) items_s[j] = items[b*NS_ + j];
    __syncthreads();

#pragma unroll
    for (int i = 0; i < NS_; i++) xs[i][j] = emb[items_s[i]*H_ + j];
    __syncthreads();

    // m = x @ G  (into hid rows 0..15)
    {
        float mcol[NS_];
#pragma unroll
        for (int i = 0; i < NS_; i++) mcol[i] = 0.f;
#pragma unroll 4
        for (int k = 0; k < H_; k++) {
            float gk = G[k*H_ + j];
#pragma unroll
            for (int i = 0; i < NS_; i++) mcol[i] += xs[i][k] * gk;
        }
#pragma unroll
        for (int i = 0; i < NS_; i++) hid[i][j] = mcol[i];
    }

    // agg = segment_sum (column-local)
#pragma unroll
    for (int i = 0; i < NS_; i++) aggs[i][j] = 0.f;
    {
        const int* src = edge + b*EPS_;
        const int* dst = edge + B_*EPS_ + b*EPS_;
#pragma unroll
        for (int e = 0; e < EPS_; e++) {
            int s = src[e] - b*NS_;
            int d = dst[e] - b*NS_;
            aggs[d][j] += hid[s][j];
        }
    }
    __syncthreads();

    // GRU (two halves of 8 rows)
    {
        const float* wih = wt + OW_IH;
        const float* whh = wt + OW_HH;
        float bi0 = b_ih[j], bi1 = b_ih[H_ + j], bi2 = b_ih[2*H_ + j];
        float bh0 = b_hh[j], bh1 = b_hh[H_ + j], bh2 = b_hh[2*H_ + j];
#pragma unroll
        for (int half = 0; half < 2; half++) {
            float gi0[8], gi1[8], gi2[8], gh0[8], gh1[8], gh2[8];
#pragma unroll
            for (int i = 0; i < 8; i++) {
                gi0[i] = bi0; gi1[i] = bi1; gi2[i] = bi2;
                gh0[i] = bh0; gh1[i] = bh1; gh2[i] = bh2;
            }
#pragma unroll 2
            for (int k = 0; k < H_; k++) {
                float wi0 = wih[k*384 + j], wi1 = wih[k*384 + H_ + j], wi2 = wih[k*384 + 2*H_ + j];
                float wh0 = whh[k*384 + j], wh1 = whh[k*384 + H_ + j], wh2 = whh[k*384 + 2*H_ + j];
#pragma unroll
                for (int i = 0; i < 8; i++) {
                    float ak = aggs[half*8 + i][k];
                    float xk = xs[half*8 + i][k];
                    gi0[i] += ak*wi0; gi1[i] += ak*wi1; gi2[i] += ak*wi2;
                    gh0[i] += xk*wh0; gh1[i] += xk*wh1; gh2[i] += xk*wh2;
                }
            }
            __syncthreads();   // finish READING xs rows before writing them
#pragma unroll
            for (int i = 0; i < 8; i++) {
                float r = 1.f / (1.f + expf(-(gi0[i] + gh0[i])));
                float z = 1.f / (1.f + expf(-(gi1[i] + gh1[i])));
                float n = tanhf(gi2[i] + r*gh2[i]);
                xs[half*8 + i][j] = (1.f - z)*n + z*xs[half*8 + i][j];
            }
        }
    }

    // hidden (column-local)
#pragma unroll
    for (int l = 0; l < L_; l++) {
        int s = seq[b*L_ + l];
        float v = 0.f;
        if (s != 0) {
            int idx = -1;
#pragma unroll
            for (int q = 0; q < NS_; q++) if (idx < 0 && items_s[q] == s) idx = q;
            v = (idx >= 0) ? xs[idx][j] : emb[s*H_ + j];
        }
        hid[l][j] = v;
    }
    int len = 0;
#pragma unroll
    for (int l = 0; l < L_; l++) len += mask[b*L_ + l];
    __syncthreads();

    // attention (single reduction phase) + hybrid + layernorm + split2 epilogue
    {
        const float* w1t = wt + OW_1;
        const float* w2t = wt + OW_2;
        const float* wtt = wt + OW_T;
        const float* ht = hid[len - 1];
        float q1 = b1[j];
#pragma unroll 8
        for (int k = 0; k < H_; k++) q1 += ht[k] * w1t[k*H_ + j];
        float w3j = w3[j];
        float bb2 = b2[j];

        for (int l = 0; l < L_; l++) {
            float q2 = bb2;
#pragma unroll 8
            for (int k = 0; k < H_; k++) q2 += hid[l][k] * w2t[k*H_ + j];
            vs[l][j] = (1.f / (1.f + expf(-(q1 + q2)))) * w3j;
        }
        __syncthreads();

        for (int l = wid; l < L_; l += 4) {
            float s = vs[l][lane] + vs[l][lane + 32] + vs[l][lane + 64] + vs[l][lane + 96];
#pragma unroll
            for (int o = 16; o > 0; o >>= 1) s += __shfl_xor_sync(0xffffffffu, s, o);
            if (lane == 0) alpha_sh[l] = s;
        }
        __syncthreads();

        float acc = 0.f;
#pragma unroll
        for (int l = 0; l < L_; l++)
            acc += alpha_sh[l] * hid[l][j] * (float)mask[b*L_ + l];
        a_sh[j] = acc;
        __syncthreads();

        float o = bt[j];
#pragma unroll 8
        for (int k = 0; k < H_; k++) o += a_sh[k] * wtt[k*H_ + j];
#pragma unroll 8
        for (int k = 0; k < H_; k++) o += ht[k] * wtt[(H_ + k)*H_ + j];

        float mu = bsum128(o, red) * (1.f / H_);
        float d = o - mu;
        float var = bsum128(d*d, red) * (1.f / H_);
        float aout = d * rsqrtf(var + 1e-5f) * gamma[j] + beta[j];

        __nv_bfloat16 h = __float2bfloat16(aout);
        __nv_bfloat16 lo = __float2bfloat16(aout - __bfloat162float(h));
        a2[b*256 + j]       = h;
        a2[b*256 + H_ + j]  = lo;
    }
}

// =================================================================================
extern "C" void kernel_launch(void* const* d_in, const int* in_sizes, int n_in,
                              void* d_out, int out_size)
{
    const int*   items    = (const int*)d_in[0];
    const int*   edge     = (const int*)d_in[1];
    const int*   sequence = (const int*)d_in[2];
    const int*   mask     = (const int*)d_in[3];
    const float* emb      = (const float*)d_in[4];
    const float* ggnn_w   = (const float*)d_in[5];
    const float* W_ih     = (const float*)d_in[6];
    const float* W_hh     = (const float*)d_in[7];
    const float* b_ih     = (const float*)d_in[8];
    const float* b_hh     = (const float*)d_in[9];
    const float* W1       = (const float*)d_in[10];
    const float* b1       = (const float*)d_in[11];
    const float* W2       = (const float*)d_in[12];
    const float* b2       = (const float*)d_in[13];
    const float* w3       = (const float*)d_in[14];
    const float* Wt       = (const float*)d_in[15];
    const float* bt       = (const float*)d_in[16];
    const float* gamma    = (const float*)d_in[17];
    const float* beta     = (const float*)d_in[18];
    float* out = (float*)d_out;

    __nv_bfloat16 *pe2, *pa2;
    float* pwt;
    cudaGetSymbolAddress((void**)&pe2, g_e2);
    cudaGetSymbolAddress((void**)&pa2, g_a2);
    cudaGetSymbolAddress((void**)&pwt, g_wt);

    cudaFuncSetAttribute(scores_mma_k, cudaFuncAttributeMaxDynamicSharedMemorySize, TCS_SMEM);

    // 1) fused prep: embedding split2 + weight transposes
    prep_k<<<NBS_SPLIT + NBW_WT, 256>>>(emb + H_, pe2, W_ih, W_hh, W1, W2, Wt, pwt);
    // 2) fused per-session pipeline -> a2[512,256]
    mega_k<<<B_, 128>>>(items, edge, sequence, mask, emb, ggnn_w, pwt,
                        b_ih, b_hh, b1, b2, w3, bt, gamma, beta, pa2);
    // 3) tensor-core scores, 64x128 tiles, 2 CTAs/SM
    scores_mma_k<<<dim3(B_/64, (V_ - 1 + 127)/128), 256, TCS_SMEM>>>(pa2, pe2, out, V_ - 1);
}